// round 4
// baseline (speedup 1.0000x reference)
#include <cuda_runtime.h>
#include <math_constants.h>

#define BB 4
#define C 256
#define L 2048
#define H 8
#define D 32

// ---------------- device scratch (no allocations allowed) ----------------
__device__ float g_weff[3 * C * C];
__device__ float g_beff[3 * C];
__device__ float g_qp[BB * C * L];
__device__ float g_kp[BB * C * L];
__device__ float g_vp[BB * C * L];
__device__ float g_att[BB * C * L];

// ---------------- packed f32x2 helpers (sm_103a) ----------------
typedef unsigned long long u64;

__device__ __forceinline__ u64 pk2(float lo, float hi) {
    u64 r;
    asm("mov.b64 %0, {%1, %2};" : "=l"(r) : "f"(lo), "f"(hi));
    return r;
}
__device__ __forceinline__ void unpk2(float& lo, float& hi, u64 v) {
    asm("mov.b64 {%0, %1}, %2;" : "=f"(lo), "=f"(hi) : "l"(v));
}
__device__ __forceinline__ u64 ffma2(u64 a, u64 b, u64 c) {
    u64 d;
    asm("fma.rn.f32x2 %0, %1, %2, %3;" : "=l"(d) : "l"(a), "l"(b), "l"(c));
    return d;
}
__device__ __forceinline__ u64 fmul2(u64 a, u64 b) {
    u64 d;
    asm("mul.rn.f32x2 %0, %1, %2;" : "=l"(d) : "l"(a), "l"(b));
    return d;
}

// ---------------- fold BN into conv weights ----------------
__global__ void fold_kernel(const float* __restrict__ w, const float* __restrict__ b,
                            const float* __restrict__ g, const float* __restrict__ beta,
                            const float* __restrict__ mean, const float* __restrict__ var,
                            float* __restrict__ weff, float* __restrict__ beff) {
    int o = blockIdx.x;
    float s = g[o] * rsqrtf(var[o] + 1e-5f);
    for (int c = threadIdx.x; c < C; c += blockDim.x)
        weff[o * C + c] = w[o * C + c] * s;
    if (threadIdx.x == 0)
        beff[o] = (b[o] - mean[o]) * s + beta[o];
}

// ---------------- generic 1x1-conv GEMM (f32x2 packed) ----------------
// OUT[b,o,l] = sum_c W[o,c]*(X[b,c,l] + PE?[c,l]) + bias[o] + RES?[b,o,l]
// 64x64 tile, 256 threads, 4(o)x4(l) microtile; accumulators packed in o-pairs.
__global__ void __launch_bounds__(256) proj_kernel(
    const float* __restrict__ X, const float* __restrict__ PE,
    const float* __restrict__ W, const float* __restrict__ bias,
    const float* __restrict__ RES, float* __restrict__ OUT) {
    __shared__ float As[16][64];   // [c_sub][o_local]
    __shared__ float Bs[16][64];   // [c_sub][l_local]

    int bIdx = blockIdx.z;
    int o0 = blockIdx.y * 64;
    int l0 = blockIdx.x * 64;
    int t  = threadIdx.x;
    int tx = t & 15, ty = t >> 4;

    const float* Xb = X + (size_t)bIdx * C * L;
    u64 acc2[2][4] = {};  // [o-pair][l]; lanes = (o=2ip, o=2ip+1)

    for (int c0 = 0; c0 < C; c0 += 16) {
        {
            int kk = t & 15, oo = t >> 4;
#pragma unroll
            for (int it = 0; it < 4; it++)
                As[kk][oo + 16 * it] = W[(o0 + oo + 16 * it) * C + c0 + kk];
        }
        {
            int ll = t & 63, kk = t >> 6;
#pragma unroll
            for (int it = 0; it < 4; it++) {
                int c = c0 + kk + 4 * it;
                float v = Xb[c * L + l0 + ll];
                if (PE) v += PE[c * L + l0 + ll];
                Bs[kk + 4 * it][ll] = v;
            }
        }
        __syncthreads();
#pragma unroll
        for (int kk = 0; kk < 16; kk++) {
            // a-pairs (a[2ip], a[2ip+1]) come directly from the 16B smem read
            ulonglong2 ap = *(const ulonglong2*)&As[kk][ty * 4];
            float4 b4 = *(const float4*)&Bs[kk][tx * 4];
            u64 bd[4] = {pk2(b4.x, b4.x), pk2(b4.y, b4.y),
                         pk2(b4.z, b4.z), pk2(b4.w, b4.w)};
#pragma unroll
            for (int j = 0; j < 4; j++) {
                acc2[0][j] = ffma2(ap.x, bd[j], acc2[0][j]);
                acc2[1][j] = ffma2(ap.y, bd[j], acc2[1][j]);
            }
        }
        __syncthreads();
    }

#pragma unroll
    for (int ip = 0; ip < 2; ip++) {
        int oA = o0 + ty * 4 + 2 * ip;
        float biA = bias[oA], biB = bias[oA + 1];
        size_t rowA = ((size_t)bIdx * C + oA) * L;
        size_t rowB = rowA + L;
#pragma unroll
        for (int j = 0; j < 4; j++) {
            int l = l0 + tx * 4 + j;
            float vA, vB;
            unpk2(vA, vB, acc2[ip][j]);
            vA += biA; vB += biB;
            if (RES) { vA += RES[rowA + l]; vB += RES[rowB + l]; }
            OUT[rowA + l] = vA;
            OUT[rowB + l] = vB;
        }
    }
}

// ---------------- flash attention (fp32, online softmax, f32x2, 2q/thread) ----
// One block per (b, h, 256-query tile); 128 threads; thread owns queries
// lq0 and lq0+128. K/V smem (128-key tiles) amortized over both queries:
// per key: 16 LDS.128 (shared) + 64 FFMA2 (2 queries) -> pure FMA-pipe bound.
// q pre-scaled by (1/sqrt(D))*log2(e); softmax in exp2 domain.
__global__ void __launch_bounds__(128) attn_kernel(
    const float* __restrict__ qp, const float* __restrict__ kp,
    const float* __restrict__ vp, float* __restrict__ outa) {
    __shared__ float4 Ks4[D / 4][128];
    __shared__ float4 Vs4[D / 4][128];

    int b = blockIdx.z, h = blockIdx.y;
    int tid = threadIdx.x;
    int lq0 = blockIdx.x * 256 + tid;   // second query: lq0 + 128
    int cbase = b * C + h * D;
    const float scale = 0.17677669529663687f * 1.4426950408889634f;  // (1/sqrt(32))*log2(e)

    u64 q2[2][D / 2], acc2[2][D / 2];
#pragma unroll
    for (int iq = 0; iq < 2; iq++)
#pragma unroll
        for (int i = 0; i < D / 2; i++) {
            size_t base = (size_t)(cbase + 2 * i) * L + lq0 + 128 * iq;
            q2[iq][i] = pk2(qp[base] * scale, qp[base + L] * scale);
            acc2[iq][i] = 0ull;
        }
    float m[2] = {-CUDART_INF_F, -CUDART_INF_F};
    float lsum[2] = {0.f, 0.f};

    for (int kt = 0; kt < L; kt += 128) {
        __syncthreads();
#pragma unroll
        for (int g = 0; g < D / 4; g++) {
            size_t base = (size_t)(cbase + 4 * g) * L + kt + tid;
            Ks4[g][tid] = make_float4(kp[base], kp[base + L], kp[base + 2 * L], kp[base + 3 * L]);
            Vs4[g][tid] = make_float4(vp[base], vp[base + L], vp[base + 2 * L], vp[base + 3 * L]);
        }
        __syncthreads();

#pragma unroll 2
        for (int j = 0; j < 128; j++) {
            ulonglong2 kx[D / 4];
#pragma unroll
            for (int g = 0; g < D / 4; g++)
                kx[g] = *(const ulonglong2*)&Ks4[g][j];
            ulonglong2 vx[D / 4];
#pragma unroll
            for (int g = 0; g < D / 4; g++)
                vx[g] = *(const ulonglong2*)&Vs4[g][j];

#pragma unroll
            for (int iq = 0; iq < 2; iq++) {
                u64 s2 = 0ull;
#pragma unroll
                for (int g = 0; g < D / 4; g++) {
                    s2 = ffma2(q2[iq][2 * g], kx[g].x, s2);
                    s2 = ffma2(q2[iq][2 * g + 1], kx[g].y, s2);
                }
                float slo, shi;
                unpk2(slo, shi, s2);
                float s = slo + shi;  // score in log2 domain

                if (s > m[iq]) {  // rare: rescale packed state
                    float corr = exp2f(m[iq] - s);
                    u64 corr2 = pk2(corr, corr);
                    lsum[iq] *= corr;
#pragma unroll
                    for (int i = 0; i < D / 2; i++)
                        acc2[iq][i] = fmul2(acc2[iq][i], corr2);
                    m[iq] = s;
                }
                float p = exp2f(s - m[iq]);
                lsum[iq] += p;
                u64 p2 = pk2(p, p);
#pragma unroll
                for (int g = 0; g < D / 4; g++) {
                    acc2[iq][2 * g]     = ffma2(p2, vx[g].x, acc2[iq][2 * g]);
                    acc2[iq][2 * g + 1] = ffma2(p2, vx[g].y, acc2[iq][2 * g + 1]);
                }
            }
        }
    }

#pragma unroll
    for (int iq = 0; iq < 2; iq++) {
        float inv = 1.f / lsum[iq];
#pragma unroll
        for (int i = 0; i < D / 2; i++) {
            float alo, ahi;
            unpk2(alo, ahi, acc2[iq][i]);
            size_t base = (size_t)(cbase + 2 * i) * L + lq0 + 128 * iq;
            outa[base]     = alo * inv;
            outa[base + L] = ahi * inv;
        }
    }
}

// ---------------- launch ----------------
extern "C" void kernel_launch(void* const* d_in, const int* in_sizes, int n_in,
                              void* d_out, int out_size) {
    const float* v     = (const float*)d_in[0];
    const float* k     = (const float*)d_in[1];
    const float* q     = (const float*)d_in[2];
    const float* pe_q  = (const float*)d_in[3];
    const float* pe_vk = (const float*)d_in[4];
    const float* wq = (const float*)d_in[5],  *bq = (const float*)d_in[6];
    const float* gq = (const float*)d_in[7],  *betaq = (const float*)d_in[8];
    const float* mq = (const float*)d_in[9],  *varq = (const float*)d_in[10];
    const float* wk = (const float*)d_in[11], *bk = (const float*)d_in[12];
    const float* gk = (const float*)d_in[13], *betak = (const float*)d_in[14];
    const float* mk = (const float*)d_in[15], *vark = (const float*)d_in[16];
    const float* wv = (const float*)d_in[17], *bv = (const float*)d_in[18];
    const float* gv = (const float*)d_in[19], *betav = (const float*)d_in[20];
    const float* mv = (const float*)d_in[21], *varv = (const float*)d_in[22];
    const float* wo = (const float*)d_in[23], *bo = (const float*)d_in[24];
    float* out = (float*)d_out;

    float *p_weff, *p_beff, *p_qp, *p_kp, *p_vp, *p_att;
    cudaGetSymbolAddress((void**)&p_weff, g_weff);
    cudaGetSymbolAddress((void**)&p_beff, g_beff);
    cudaGetSymbolAddress((void**)&p_qp,  g_qp);
    cudaGetSymbolAddress((void**)&p_kp,  g_kp);
    cudaGetSymbolAddress((void**)&p_vp,  g_vp);
    cudaGetSymbolAddress((void**)&p_att, g_att);

    // fold BN into projection weights
    fold_kernel<<<C, 256>>>(wq, bq, gq, betaq, mq, varq, p_weff + 0 * C * C, p_beff + 0 * C);
    fold_kernel<<<C, 256>>>(wk, bk, gk, betak, mk, vark, p_weff + 1 * C * C, p_beff + 1 * C);
    fold_kernel<<<C, 256>>>(wv, bv, gv, betav, mv, varv, p_weff + 2 * C * C, p_beff + 2 * C);

    dim3 pgrid(L / 64, C / 64, BB);
    // projections (PE folded into the GEMM input)
    proj_kernel<<<pgrid, 256>>>(q, pe_q,  p_weff + 0 * C * C, p_beff + 0 * C, nullptr, p_qp);
    proj_kernel<<<pgrid, 256>>>(k, pe_vk, p_weff + 1 * C * C, p_beff + 1 * C, nullptr, p_kp);
    proj_kernel<<<pgrid, 256>>>(v, pe_vk, p_weff + 2 * C * C, p_beff + 2 * C, nullptr, p_vp);

    // attention (2 queries per thread, 256-query tiles)
    attn_kernel<<<dim3(L / 256, H, BB), 128>>>(p_qp, p_kp, p_vp, p_att);

    // output projection + residual
    proj_kernel<<<pgrid, 256>>>(p_att, nullptr, wo, bo, q, out);
}

// round 5
// speedup vs baseline: 1.0541x; 1.0541x over previous
#include <cuda_runtime.h>
#include <math_constants.h>

#define BB 4
#define C 256
#define L 2048
#define H 8
#define D 32

// ---------------- device scratch (no allocations allowed) ----------------
__device__ float g_weff[4 * C * C];   // slots 0..2: folded q/k/v (transposed); 3: wo^T
__device__ float g_beff[3 * C];
__device__ float g_qp[BB * C * L];
__device__ float g_kp[BB * C * L];
__device__ float g_vp[BB * C * L];
__device__ float g_att[BB * C * L];

// ---------------- packed f32x2 helpers (sm_103a) ----------------
typedef unsigned long long u64;

__device__ __forceinline__ u64 pk2(float lo, float hi) {
    u64 r;
    asm("mov.b64 %0, {%1, %2};" : "=l"(r) : "f"(lo), "f"(hi));
    return r;
}
__device__ __forceinline__ void unpk2(float& lo, float& hi, u64 v) {
    asm("mov.b64 {%0, %1}, %2;" : "=f"(lo), "=f"(hi) : "l"(v));
}
__device__ __forceinline__ u64 ffma2(u64 a, u64 b, u64 c) {
    u64 d;
    asm("fma.rn.f32x2 %0, %1, %2, %3;" : "=l"(d) : "l"(a), "l"(b), "l"(c));
    return d;
}
__device__ __forceinline__ u64 fmul2(u64 a, u64 b) {
    u64 d;
    asm("mul.rn.f32x2 %0, %1, %2;" : "=l"(d) : "l"(a), "l"(b));
    return d;
}
__device__ __forceinline__ float ex2(float x) {  // MUFU.EX2 regardless of compile flags
    float y;
    asm("ex2.approx.ftz.f32 %0, %1;" : "=f"(y) : "f"(x));
    return y;
}

// ---------------- fold BN into conv weights (emit TRANSPOSED [c][o]) ------
__global__ void fold_kernel(const float* __restrict__ w, const float* __restrict__ b,
                            const float* __restrict__ g, const float* __restrict__ beta,
                            const float* __restrict__ mean, const float* __restrict__ var,
                            float* __restrict__ weff_t, float* __restrict__ beff) {
    int o = blockIdx.x;
    float s = g[o] * rsqrtf(var[o] + 1e-5f);
    for (int c = threadIdx.x; c < C; c += blockDim.x)
        weff_t[c * C + o] = w[o * C + c] * s;   // transposed store
    if (threadIdx.x == 0)
        beff[o] = (b[o] - mean[o]) * s + beta[o];
}

// plain transpose for wo
__global__ void transpose_kernel(const float* __restrict__ src, float* __restrict__ dst) {
    int o = blockIdx.x;
    for (int c = threadIdx.x; c < C; c += blockDim.x)
        dst[c * C + o] = src[o * C + c];
}

// ---------------- generic 1x1-conv GEMM (f32x2 packed, Wt = [c][o]) -------
// OUT[b,o,l] = sum_c Wt[c,o]*(X[b,c,l] + PE?[c,l]) + bias[o] + RES?[b,o,l]
// 64x64 tile, 256 threads, 4(o)x4(l) microtile; accumulators packed in o-pairs.
// Both smem tiles are loaded coalesced and stored conflict-free.
__global__ void __launch_bounds__(256) proj_kernel(
    const float* __restrict__ X, const float* __restrict__ PE,
    const float* __restrict__ Wt, const float* __restrict__ bias,
    const float* __restrict__ RES, float* __restrict__ OUT) {
    __shared__ float As[16][64];   // [c_sub][o_local]
    __shared__ float Bs[16][64];   // [c_sub][l_local]

    int bIdx = blockIdx.z;
    int o0 = blockIdx.y * 64;
    int l0 = blockIdx.x * 64;
    int t  = threadIdx.x;
    int tx = t & 15, ty = t >> 4;

    const float* Xb = X + (size_t)bIdx * C * L;
    u64 acc2[2][4] = {};  // [o-pair][l]

    int ll = t & 63, kk4 = t >> 6;
    for (int c0 = 0; c0 < C; c0 += 16) {
#pragma unroll
        for (int it = 0; it < 4; it++) {
            int cs = kk4 + 4 * it;
            int c = c0 + cs;
            As[cs][ll] = Wt[c * C + o0 + ll];          // coalesced, no conflicts
            float v = Xb[c * L + l0 + ll];
            if (PE) v += PE[c * L + l0 + ll];
            Bs[cs][ll] = v;                             // coalesced, no conflicts
        }
        __syncthreads();
#pragma unroll
        for (int kk = 0; kk < 16; kk++) {
            ulonglong2 ap = *(const ulonglong2*)&As[kk][ty * 4];  // o-pairs, free from 16B read
            float4 b4 = *(const float4*)&Bs[kk][tx * 4];
            u64 bd[4] = {pk2(b4.x, b4.x), pk2(b4.y, b4.y),
                         pk2(b4.z, b4.z), pk2(b4.w, b4.w)};
#pragma unroll
            for (int j = 0; j < 4; j++) {
                acc2[0][j] = ffma2(ap.x, bd[j], acc2[0][j]);
                acc2[1][j] = ffma2(ap.y, bd[j], acc2[1][j]);
            }
        }
        __syncthreads();
    }

#pragma unroll
    for (int ip = 0; ip < 2; ip++) {
        int oA = o0 + ty * 4 + 2 * ip;
        float biA = bias[oA], biB = bias[oA + 1];
        size_t rowA = ((size_t)bIdx * C + oA) * L;
        size_t rowB = rowA + L;
#pragma unroll
        for (int j = 0; j < 4; j++) {
            int l = l0 + tx * 4 + j;
            float vA, vB;
            unpk2(vA, vB, acc2[ip][j]);
            vA += biA; vB += biB;
            if (RES) { vA += RES[rowA + l]; vB += RES[rowB + l]; }
            OUT[rowA + l] = vA;
            OUT[rowB + l] = vB;
        }
    }
}

// ---------------- flash attention (fp32, online softmax, f32x2, 2q/thread) ----
// One block per (b, h, 256-query tile); 128 threads; thread owns queries
// lq0 and lq0+128. K/V smem amortized over both queries. QK uses 4 partial
// accumulators (chain depth 8). exp forced to MUFU via ex2.approx.
__global__ void __launch_bounds__(128) attn_kernel(
    const float* __restrict__ qp, const float* __restrict__ kp,
    const float* __restrict__ vp, float* __restrict__ outa) {
    __shared__ float4 Ks4[D / 4][128];
    __shared__ float4 Vs4[D / 4][128];

    int b = blockIdx.z, h = blockIdx.y;
    int tid = threadIdx.x;
    int lq0 = blockIdx.x * 256 + tid;   // second query: lq0 + 128
    int cbase = b * C + h * D;
    const float scale = 0.17677669529663687f * 1.4426950408889634f;  // (1/sqrt(32))*log2(e)

    u64 q2[2][D / 2], acc2[2][D / 2];
#pragma unroll
    for (int iq = 0; iq < 2; iq++)
#pragma unroll
        for (int i = 0; i < D / 2; i++) {
            size_t base = (size_t)(cbase + 2 * i) * L + lq0 + 128 * iq;
            q2[iq][i] = pk2(qp[base] * scale, qp[base + L] * scale);
            acc2[iq][i] = 0ull;
        }
    float m[2] = {-CUDART_INF_F, -CUDART_INF_F};
    float lsum[2] = {0.f, 0.f};

    for (int kt = 0; kt < L; kt += 128) {
        __syncthreads();
#pragma unroll
        for (int g = 0; g < D / 4; g++) {
            size_t base = (size_t)(cbase + 4 * g) * L + kt + tid;
            Ks4[g][tid] = make_float4(kp[base], kp[base + L], kp[base + 2 * L], kp[base + 3 * L]);
            Vs4[g][tid] = make_float4(vp[base], vp[base + L], vp[base + 2 * L], vp[base + 3 * L]);
        }
        __syncthreads();

#pragma unroll 2
        for (int j = 0; j < 128; j++) {
            // QK: 4 partial sums (2 per query) -> chain depth 8
            u64 sA0 = 0ull, sB0 = 0ull, sA1 = 0ull, sB1 = 0ull;
#pragma unroll
            for (int g = 0; g < D / 4; g++) {
                ulonglong2 kx = *(const ulonglong2*)&Ks4[g][j];
                sA0 = ffma2(q2[0][2 * g],     kx.x, sA0);
                sB0 = ffma2(q2[0][2 * g + 1], kx.y, sB0);
                sA1 = ffma2(q2[1][2 * g],     kx.x, sA1);
                sB1 = ffma2(q2[1][2 * g + 1], kx.y, sB1);
            }
            float s[2];
            {
                float xa, xb, ya, yb;
                unpk2(xa, xb, sA0); unpk2(ya, yb, sB0);
                s[0] = (xa + xb) + (ya + yb);
                unpk2(xa, xb, sA1); unpk2(ya, yb, sB1);
                s[1] = (xa + xb) + (ya + yb);
            }

            u64 p2q[2];
#pragma unroll
            for (int iq = 0; iq < 2; iq++) {
                if (s[iq] > m[iq]) {  // rare: rescale packed state
                    float corr = ex2(m[iq] - s[iq]);
                    u64 corr2 = pk2(corr, corr);
                    lsum[iq] *= corr;
#pragma unroll
                    for (int i = 0; i < D / 2; i++)
                        acc2[iq][i] = fmul2(acc2[iq][i], corr2);
                    m[iq] = s[iq];
                }
                float p = ex2(s[iq] - m[iq]);
                lsum[iq] += p;
                p2q[iq] = pk2(p, p);
            }

#pragma unroll
            for (int g = 0; g < D / 4; g++) {
                ulonglong2 vx = *(const ulonglong2*)&Vs4[g][j];
                acc2[0][2 * g]     = ffma2(p2q[0], vx.x, acc2[0][2 * g]);
                acc2[0][2 * g + 1] = ffma2(p2q[0], vx.y, acc2[0][2 * g + 1]);
                acc2[1][2 * g]     = ffma2(p2q[1], vx.x, acc2[1][2 * g]);
                acc2[1][2 * g + 1] = ffma2(p2q[1], vx.y, acc2[1][2 * g + 1]);
            }
        }
    }

#pragma unroll
    for (int iq = 0; iq < 2; iq++) {
        float inv = 1.f / lsum[iq];
#pragma unroll
        for (int i = 0; i < D / 2; i++) {
            float alo, ahi;
            unpk2(alo, ahi, acc2[iq][i]);
            size_t base = (size_t)(cbase + 2 * i) * L + lq0 + 128 * iq;
            outa[base]     = alo * inv;
            outa[base + L] = ahi * inv;
        }
    }
}

// ---------------- launch ----------------
extern "C" void kernel_launch(void* const* d_in, const int* in_sizes, int n_in,
                              void* d_out, int out_size) {
    const float* v     = (const float*)d_in[0];
    const float* k     = (const float*)d_in[1];
    const float* q     = (const float*)d_in[2];
    const float* pe_q  = (const float*)d_in[3];
    const float* pe_vk = (const float*)d_in[4];
    const float* wq = (const float*)d_in[5],  *bq = (const float*)d_in[6];
    const float* gq = (const float*)d_in[7],  *betaq = (const float*)d_in[8];
    const float* mq = (const float*)d_in[9],  *varq = (const float*)d_in[10];
    const float* wk = (const float*)d_in[11], *bk = (const float*)d_in[12];
    const float* gk = (const float*)d_in[13], *betak = (const float*)d_in[14];
    const float* mk = (const float*)d_in[15], *vark = (const float*)d_in[16];
    const float* wv = (const float*)d_in[17], *bv = (const float*)d_in[18];
    const float* gv = (const float*)d_in[19], *betav = (const float*)d_in[20];
    const float* mv = (const float*)d_in[21], *varv = (const float*)d_in[22];
    const float* wo = (const float*)d_in[23], *bo = (const float*)d_in[24];
    float* out = (float*)d_out;

    float *p_weff, *p_beff, *p_qp, *p_kp, *p_vp, *p_att;
    cudaGetSymbolAddress((void**)&p_weff, g_weff);
    cudaGetSymbolAddress((void**)&p_beff, g_beff);
    cudaGetSymbolAddress((void**)&p_qp,  g_qp);
    cudaGetSymbolAddress((void**)&p_kp,  g_kp);
    cudaGetSymbolAddress((void**)&p_vp,  g_vp);
    cudaGetSymbolAddress((void**)&p_att, g_att);

    // fold BN into projection weights (transposed) + transpose wo
    fold_kernel<<<C, 256>>>(wq, bq, gq, betaq, mq, varq, p_weff + 0 * C * C, p_beff + 0 * C);
    fold_kernel<<<C, 256>>>(wk, bk, gk, betak, mk, vark, p_weff + 1 * C * C, p_beff + 1 * C);
    fold_kernel<<<C, 256>>>(wv, bv, gv, betav, mv, varv, p_weff + 2 * C * C, p_beff + 2 * C);
    transpose_kernel<<<C, 256>>>(wo, p_weff + 3 * C * C);

    dim3 pgrid(L / 64, C / 64, BB);
    // projections (PE folded into the GEMM input)
    proj_kernel<<<pgrid, 256>>>(q, pe_q,  p_weff + 0 * C * C, p_beff + 0 * C, nullptr, p_qp);
    proj_kernel<<<pgrid, 256>>>(k, pe_vk, p_weff + 1 * C * C, p_beff + 1 * C, nullptr, p_kp);
    proj_kernel<<<pgrid, 256>>>(v, pe_vk, p_weff + 2 * C * C, p_beff + 2 * C, nullptr, p_vp);

    // attention (2 queries per thread, 256-query tiles)
    attn_kernel<<<dim3(L / 256, H, BB), 128>>>(p_qp, p_kp, p_vp, p_att);

    // output projection + residual
    proj_kernel<<<pgrid, 256>>>(p_att, nullptr, p_weff + 3 * C * C, bo, q, out);
}

// round 6
// speedup vs baseline: 2.4655x; 2.3390x over previous
#include <cuda_runtime.h>
#include <math_constants.h>
#include <cstdint>

#define BB 4
#define C 256
#define L 2048
#define H 8
#define D 32
#define NQT 64   // queries per block
#define NKT 64   // keys per tile

// ---------------- device scratch (no allocations allowed) ----------------
__device__ float g_weff[4 * C * C];   // 0..2: folded q/k/v (transposed); 3: wo^T
__device__ float g_beff[3 * C];
__device__ float g_qp[BB * C * L];
__device__ float g_kp[BB * C * L];
__device__ float g_vp[BB * C * L];
__device__ float g_att[BB * C * L];

// ---------------- helpers ----------------
typedef unsigned long long u64;

__device__ __forceinline__ u64 pk2(float lo, float hi) {
    u64 r;
    asm("mov.b64 %0, {%1, %2};" : "=l"(r) : "f"(lo), "f"(hi));
    return r;
}
__device__ __forceinline__ void unpk2(float& lo, float& hi, u64 v) {
    asm("mov.b64 {%0, %1}, %2;" : "=f"(lo), "=f"(hi) : "l"(v));
}
__device__ __forceinline__ u64 ffma2(u64 a, u64 b, u64 c) {
    u64 d;
    asm("fma.rn.f32x2 %0, %1, %2, %3;" : "=l"(d) : "l"(a), "l"(b), "l"(c));
    return d;
}
__device__ __forceinline__ float ex2(float x) {
    float y;
    asm("ex2.approx.ftz.f32 %0, %1;" : "=f"(y) : "f"(x));
    return y;
}
__device__ __forceinline__ uint32_t f2tf32(float x) {
    uint32_t r;
    asm("cvt.rna.tf32.f32 %0, %1;" : "=r"(r) : "f"(x));
    return r;
}
// packs: hi -> upper 16 bits, lo -> lower 16 bits
__device__ __forceinline__ uint32_t bfpk(float hi, float lo) {
    uint32_t r;
    asm("cvt.rn.bf16x2.f32 %0, %1, %2;" : "=r"(r) : "f"(hi), "f"(lo));
    return r;
}
__device__ __forceinline__ void mma_tf32(float c[4], const uint32_t a[4],
                                         uint32_t b0, uint32_t b1) {
    asm volatile(
        "mma.sync.aligned.m16n8k8.row.col.f32.tf32.tf32.f32 "
        "{%0,%1,%2,%3},{%4,%5,%6,%7},{%8,%9},{%0,%1,%2,%3};"
        : "+f"(c[0]), "+f"(c[1]), "+f"(c[2]), "+f"(c[3])
        : "r"(a[0]), "r"(a[1]), "r"(a[2]), "r"(a[3]), "r"(b0), "r"(b1));
}
__device__ __forceinline__ void mma_bf16(float c[4], uint32_t a0, uint32_t a1,
                                         uint32_t a2, uint32_t a3,
                                         uint32_t b0, uint32_t b1) {
    asm volatile(
        "mma.sync.aligned.m16n8k16.row.col.f32.bf16.bf16.f32 "
        "{%0,%1,%2,%3},{%4,%5,%6,%7},{%8,%9},{%0,%1,%2,%3};"
        : "+f"(c[0]), "+f"(c[1]), "+f"(c[2]), "+f"(c[3])
        : "r"(a0), "r"(a1), "r"(a2), "r"(a3), "r"(b0), "r"(b1));
}

// ---------------- fold BN into conv weights + transpose wo (one launch) ----
__global__ void fold_all_kernel(
    const float* __restrict__ wq, const float* __restrict__ bq, const float* __restrict__ gq,
    const float* __restrict__ betaq, const float* __restrict__ mq, const float* __restrict__ varq,
    const float* __restrict__ wk, const float* __restrict__ bk, const float* __restrict__ gk,
    const float* __restrict__ betak, const float* __restrict__ mk, const float* __restrict__ vark,
    const float* __restrict__ wv, const float* __restrict__ bv, const float* __restrict__ gv,
    const float* __restrict__ betav, const float* __restrict__ mv, const float* __restrict__ varv,
    const float* __restrict__ wo) {
    int o = blockIdx.x;
    int slot = blockIdx.y;
    if (slot == 3) {  // transpose wo
        for (int c0 = threadIdx.x; c0 < C; c0 += blockDim.x)
            g_weff[3 * C * C + c0 * C + o] = wo[o * C + c0];
        return;
    }
    const float *w, *b, *g, *beta, *mean, *var;
    if (slot == 0) { w = wq; b = bq; g = gq; beta = betaq; mean = mq; var = varq; }
    else if (slot == 1) { w = wk; b = bk; g = gk; beta = betak; mean = mk; var = vark; }
    else { w = wv; b = bv; g = gv; beta = betav; mean = mv; var = varv; }
    float s = g[o] * rsqrtf(var[o] + 1e-5f);
    for (int c0 = threadIdx.x; c0 < C; c0 += blockDim.x)
        g_weff[slot * C * C + c0 * C + o] = w[o * C + c0] * s;   // transposed store
    if (threadIdx.x == 0)
        g_beff[slot * C + o] = (b[o] - mean[o]) * s + beta[o];
}

// ---------------- generic 1x1-conv GEMM (f32x2 packed, Wt = [c][o]) -------
__global__ void __launch_bounds__(256) proj_kernel(
    const float* __restrict__ X, const float* __restrict__ PE,
    const float* __restrict__ Wt, const float* __restrict__ bias,
    const float* __restrict__ RES, float* __restrict__ OUT) {
    __shared__ float As[16][64];   // [c_sub][o_local]
    __shared__ float Bs[16][64];   // [c_sub][l_local]

    int bIdx = blockIdx.z;
    int o0 = blockIdx.y * 64;
    int l0 = blockIdx.x * 64;
    int t  = threadIdx.x;
    int tx = t & 15, ty = t >> 4;

    const float* Xb = X + (size_t)bIdx * C * L;
    u64 acc2[2][4] = {};

    int ll = t & 63, kk4 = t >> 6;
    for (int c0 = 0; c0 < C; c0 += 16) {
#pragma unroll
        for (int it = 0; it < 4; it++) {
            int cs = kk4 + 4 * it;
            int c = c0 + cs;
            As[cs][ll] = Wt[c * C + o0 + ll];
            float v = Xb[c * L + l0 + ll];
            if (PE) v += PE[c * L + l0 + ll];
            Bs[cs][ll] = v;
        }
        __syncthreads();
#pragma unroll
        for (int kk = 0; kk < 16; kk++) {
            ulonglong2 ap = *(const ulonglong2*)&As[kk][ty * 4];
            float4 b4 = *(const float4*)&Bs[kk][tx * 4];
            u64 bd[4] = {pk2(b4.x, b4.x), pk2(b4.y, b4.y),
                         pk2(b4.z, b4.z), pk2(b4.w, b4.w)};
#pragma unroll
            for (int j = 0; j < 4; j++) {
                acc2[0][j] = ffma2(ap.x, bd[j], acc2[0][j]);
                acc2[1][j] = ffma2(ap.y, bd[j], acc2[1][j]);
            }
        }
        __syncthreads();
    }

#pragma unroll
    for (int ip = 0; ip < 2; ip++) {
        int oA = o0 + ty * 4 + 2 * ip;
        float biA = bias[oA], biB = bias[oA + 1];
        size_t rowA = ((size_t)bIdx * C + oA) * L;
        size_t rowB = rowA + L;
#pragma unroll
        for (int j = 0; j < 4; j++) {
            int l = l0 + tx * 4 + j;
            float vA, vB;
            unpk2(vA, vB, acc2[ip][j]);
            vA += biA; vB += biB;
            if (RES) { vA += RES[rowA + l]; vB += RES[rowB + l]; }
            OUT[rowA + l] = vA;
            OUT[rowB + l] = vB;
        }
    }
}

// ---------------- flash attention: tf32 QK + bf16 PV via mma.sync ----------
// Block = (b, h, 64-query tile), 4 warps x 16 query rows. 64-key tiles.
// K smem: two tf32 planes KtA/KtB: KtA[4k+t][key] = K[8k+t], KtB = K[8k+t+4].
//   QK B-frag (k=t,n=g): bank = 8t+g -> conflict-free (stride 72 words).
// V smem: bf16x2 Vt[d][keypair] (stride 36 words): bank = 4g+t -> conflict-free.
// Online softmax per 8-row half (quad shfl reductions); P stays in registers
// (C-frag of QK == A-frag of bf16 m16n8k16 after bf16x2 pack).
__global__ void __launch_bounds__(128) attn_kernel(
    const float* __restrict__ qp, const float* __restrict__ kp,
    const float* __restrict__ vp, float* __restrict__ outa) {
    __shared__ uint32_t KtA[16][72];
    __shared__ uint32_t KtB[16][72];
    __shared__ uint32_t Vt[32][36];

    int b = blockIdx.z, h = blockIdx.y;
    int tid = threadIdx.x;
    int w = tid >> 5, lane = tid & 31;
    int g = lane >> 2, t = lane & 3;
    int q0 = blockIdx.x * NQT;
    int cbase = b * C + h * D;
    const float scl = 0.17677669529663687f * 1.4426950408889634f;  // (1/sqrt(D))*log2(e)

    // Q fragments (tf32 m16n8k8 A-layout), loaded once
    uint32_t qa[4][4];
    {
        int qrow = q0 + 16 * w;
#pragma unroll
        for (int ks = 0; ks < 4; ks++) {
            int d0 = 8 * ks;
            qa[ks][0] = f2tf32(qp[(size_t)(cbase + d0 + t) * L + qrow + g] * scl);
            qa[ks][1] = f2tf32(qp[(size_t)(cbase + d0 + t) * L + qrow + g + 8] * scl);
            qa[ks][2] = f2tf32(qp[(size_t)(cbase + d0 + t + 4) * L + qrow + g] * scl);
            qa[ks][3] = f2tf32(qp[(size_t)(cbase + d0 + t + 4) * L + qrow + g + 8] * scl);
        }
    }

    float accPV[4][4] = {};
    float mA = -CUDART_INF_F, mB = -CUDART_INF_F, lA = 0.f, lB = 0.f;

    // register-staged prefetch
    float kreg[16];
    float2 vreg[8];
    int kd_hi = tid >> 6, kkey = tid & 63;   // K elem: d = 2p + kd_hi, key = kkey
    int vd_hi = tid >> 5, vkp = tid & 31;    // V pair: d = 4p + vd_hi, keys 2vkp..+1

#pragma unroll
    for (int p = 0; p < 16; p++)
        kreg[p] = kp[(size_t)(cbase + 2 * p + kd_hi) * L + kkey];
#pragma unroll
    for (int p = 0; p < 8; p++)
        vreg[p] = *(const float2*)&vp[(size_t)(cbase + 4 * p + vd_hi) * L + 2 * vkp];

    for (int kt = 0; kt < L; kt += NKT) {
        __syncthreads();
#pragma unroll
        for (int p = 0; p < 16; p++) {
            int d = 2 * p + kd_hi;
            int s = ((d >> 3) << 2) | (d & 3);
            uint32_t tv = f2tf32(kreg[p]);
            if (((d >> 2) & 1) == 0) KtA[s][kkey] = tv;
            else                     KtB[s][kkey] = tv;
        }
#pragma unroll
        for (int p = 0; p < 8; p++) {
            int d = 4 * p + vd_hi;
            Vt[d][vkp] = bfpk(vreg[p].y, vreg[p].x);  // lo = even key
        }
        __syncthreads();

        if (kt + NKT < L) {  // prefetch next tile (overlaps compute)
            int kn = kt + NKT;
#pragma unroll
            for (int p = 0; p < 16; p++)
                kreg[p] = kp[(size_t)(cbase + 2 * p + kd_hi) * L + kn + kkey];
#pragma unroll
            for (int p = 0; p < 8; p++)
                vreg[p] = *(const float2*)&vp[(size_t)(cbase + 4 * p + vd_hi) * L + kn + 2 * vkp];
        }

        // ---- QK: S[16 x 64] in 8 n-tiles of C-frags ----
        float c[8][4] = {};
#pragma unroll
        for (int n = 0; n < 8; n++) {
#pragma unroll
            for (int ks = 0; ks < 4; ks++) {
                uint32_t b0 = KtA[4 * ks + t][8 * n + g];
                uint32_t b1 = KtB[4 * ks + t][8 * n + g];
                mma_tf32(c[n], qa[ks], b0, b1);
            }
        }

        // ---- online softmax (log2 domain) ----
        float tA = -CUDART_INF_F, tB = -CUDART_INF_F;
#pragma unroll
        for (int n = 0; n < 8; n++) {
            tA = fmaxf(tA, fmaxf(c[n][0], c[n][1]));
            tB = fmaxf(tB, fmaxf(c[n][2], c[n][3]));
        }
        tA = fmaxf(tA, __shfl_xor_sync(0xffffffffu, tA, 1));
        tA = fmaxf(tA, __shfl_xor_sync(0xffffffffu, tA, 2));
        tB = fmaxf(tB, __shfl_xor_sync(0xffffffffu, tB, 1));
        tB = fmaxf(tB, __shfl_xor_sync(0xffffffffu, tB, 2));
        float mAn = fmaxf(mA, tA), mBn = fmaxf(mB, tB);
        float cA = ex2(mA - mAn), cB = ex2(mB - mBn);
        mA = mAn; mB = mBn;
        lA *= cA; lB *= cB;
#pragma unroll
        for (int nt = 0; nt < 4; nt++) {
            accPV[nt][0] *= cA; accPV[nt][1] *= cA;
            accPV[nt][2] *= cB; accPV[nt][3] *= cB;
        }
#pragma unroll
        for (int n = 0; n < 8; n++) {
            c[n][0] = ex2(c[n][0] - mA); c[n][1] = ex2(c[n][1] - mA);
            c[n][2] = ex2(c[n][2] - mB); c[n][3] = ex2(c[n][3] - mB);
            lA += c[n][0] + c[n][1];
            lB += c[n][2] + c[n][3];
        }

        // ---- PV: P[16 x 64] (bf16, from C-frags) x V[64 x 32] ----
#pragma unroll
        for (int kk = 0; kk < 4; kk++) {
            uint32_t a0 = bfpk(c[2 * kk][1],     c[2 * kk][0]);
            uint32_t a1 = bfpk(c[2 * kk][3],     c[2 * kk][2]);
            uint32_t a2 = bfpk(c[2 * kk + 1][1], c[2 * kk + 1][0]);
            uint32_t a3 = bfpk(c[2 * kk + 1][3], c[2 * kk + 1][2]);
#pragma unroll
            for (int nt = 0; nt < 4; nt++) {
                uint32_t b0 = Vt[8 * nt + g][8 * kk + t];
                uint32_t b1 = Vt[8 * nt + g][8 * kk + t + 4];
                mma_bf16(accPV[nt], a0, a1, a2, a3, b0, b1);
            }
        }
    }

    // lsum: quad-reduce per row-half (partials valid: corr factors shared in quad)
    lA += __shfl_xor_sync(0xffffffffu, lA, 1);
    lA += __shfl_xor_sync(0xffffffffu, lA, 2);
    lB += __shfl_xor_sync(0xffffffffu, lB, 1);
    lB += __shfl_xor_sync(0xffffffffu, lB, 2);
    float iA = 1.f / lA, iB = 1.f / lB;
    int q = q0 + 16 * w + g;
#pragma unroll
    for (int nt = 0; nt < 4; nt++) {
        int d = 8 * nt + 2 * t;
        outa[(size_t)(cbase + d) * L + q]         = accPV[nt][0] * iA;
        outa[(size_t)(cbase + d + 1) * L + q]     = accPV[nt][1] * iA;
        outa[(size_t)(cbase + d) * L + q + 8]     = accPV[nt][2] * iB;
        outa[(size_t)(cbase + d + 1) * L + q + 8] = accPV[nt][3] * iB;
    }
}

// ---------------- launch ----------------
extern "C" void kernel_launch(void* const* d_in, const int* in_sizes, int n_in,
                              void* d_out, int out_size) {
    const float* v     = (const float*)d_in[0];
    const float* k     = (const float*)d_in[1];
    const float* q     = (const float*)d_in[2];
    const float* pe_q  = (const float*)d_in[3];
    const float* pe_vk = (const float*)d_in[4];
    const float* wq = (const float*)d_in[5],  *bq = (const float*)d_in[6];
    const float* gq = (const float*)d_in[7],  *betaq = (const float*)d_in[8];
    const float* mq = (const float*)d_in[9],  *varq = (const float*)d_in[10];
    const float* wk = (const float*)d_in[11], *bk = (const float*)d_in[12];
    const float* gk = (const float*)d_in[13], *betak = (const float*)d_in[14];
    const float* mk = (const float*)d_in[15], *vark = (const float*)d_in[16];
    const float* wv = (const float*)d_in[17], *bv = (const float*)d_in[18];
    const float* gv = (const float*)d_in[19], *betav = (const float*)d_in[20];
    const float* mv = (const float*)d_in[21], *varv = (const float*)d_in[22];
    const float* wo = (const float*)d_in[23], *bo = (const float*)d_in[24];
    float* out = (float*)d_out;

    float *p_weff, *p_beff, *p_qp, *p_kp, *p_vp, *p_att;
    cudaGetSymbolAddress((void**)&p_weff, g_weff);
    cudaGetSymbolAddress((void**)&p_beff, g_beff);
    cudaGetSymbolAddress((void**)&p_qp,  g_qp);
    cudaGetSymbolAddress((void**)&p_kp,  g_kp);
    cudaGetSymbolAddress((void**)&p_vp,  g_vp);
    cudaGetSymbolAddress((void**)&p_att, g_att);

    // fold BN into weights (transposed) + transpose wo: one launch
    fold_all_kernel<<<dim3(C, 4), 256>>>(wq, bq, gq, betaq, mq, varq,
                                         wk, bk, gk, betak, mk, vark,
                                         wv, bv, gv, betav, mv, varv, wo);

    dim3 pgrid(L / 64, C / 64, BB);
    proj_kernel<<<pgrid, 256>>>(q, pe_q,  p_weff + 0 * C * C, p_beff + 0 * C, nullptr, p_qp);
    proj_kernel<<<pgrid, 256>>>(k, pe_vk, p_weff + 1 * C * C, p_beff + 1 * C, nullptr, p_kp);
    proj_kernel<<<pgrid, 256>>>(v, pe_vk, p_weff + 2 * C * C, p_beff + 2 * C, nullptr, p_vp);

    // tensor-core flash attention
    attn_kernel<<<dim3(L / NQT, H, BB), 128>>>(p_qp, p_kp, p_vp, p_att);

    // output projection + residual
    proj_kernel<<<pgrid, 256>>>(p_att, nullptr, p_weff + 3 * C * C, bo, q, out);
}

// round 9
// speedup vs baseline: 2.5555x; 1.0365x over previous
#include <cuda_runtime.h>
#include <math_constants.h>
#include <cstdint>

#define BB 4
#define C 256
#define L 2048
#define H 8
#define D 32
#define NQT 64   // attn: queries per block
#define NKT 64   // attn: keys per tile
#define PTL 32   // proj: l-cols per block
#define PTO 128  // proj: o-rows per block
#define XPAD 40  // proj smem row stride (words): bank = 8t+g+8n, conflict-free

// ---------------- device scratch (no allocations allowed) ----------------
__device__ uint32_t g_wfrag[4 * C * C];  // tf32 A-fragment-layout weights (slots 0..3)
__device__ float g_beff[3 * C];
__device__ float g_qp[BB * C * L];
__device__ float g_kp[BB * C * L];
__device__ float g_vp[BB * C * L];
__device__ float g_att[BB * C * L];

// ---------------- helpers ----------------
__device__ __forceinline__ float ex2(float x) {
    float y;
    asm("ex2.approx.ftz.f32 %0, %1;" : "=f"(y) : "f"(x));
    return y;
}
__device__ __forceinline__ uint32_t f2tf32(float x) {
    uint32_t r;
    asm("cvt.rna.tf32.f32 %0, %1;" : "=r"(r) : "f"(x));
    return r;
}
// packs: hi -> upper 16 bits, lo -> lower 16 bits
__device__ __forceinline__ uint32_t bfpk(float hi, float lo) {
    uint32_t r;
    asm("cvt.rn.bf16x2.f32 %0, %1, %2;" : "=r"(r) : "f"(hi), "f"(lo));
    return r;
}
__device__ __forceinline__ void mma_tf32(float c[4], const uint32_t a[4],
                                         uint32_t b0, uint32_t b1) {
    asm volatile(
        "mma.sync.aligned.m16n8k8.row.col.f32.tf32.tf32.f32 "
        "{%0,%1,%2,%3},{%4,%5,%6,%7},{%8,%9},{%0,%1,%2,%3};"
        : "+f"(c[0]), "+f"(c[1]), "+f"(c[2]), "+f"(c[3])
        : "r"(a[0]), "r"(a[1]), "r"(a[2]), "r"(a[3]), "r"(b0), "r"(b1));
}
__device__ __forceinline__ void mma_bf16(float c[4], uint32_t a0, uint32_t a1,
                                         uint32_t a2, uint32_t a3,
                                         uint32_t b0, uint32_t b1) {
    asm volatile(
        "mma.sync.aligned.m16n8k16.row.col.f32.bf16.bf16.f32 "
        "{%0,%1,%2,%3},{%4,%5,%6,%7},{%8,%9},{%0,%1,%2,%3};"
        : "+f"(c[0]), "+f"(c[1]), "+f"(c[2]), "+f"(c[3])
        : "r"(a0), "r"(a1), "r"(a2), "r"(a3), "r"(b0), "r"(b1));
}

// ---------------- fold BN + emit tf32 A-fragment layout -------------------
// For (o,c): ks=c/8, t=c%4, hi_k=(c>>2)&1; ob=o/16, g=(o%16)%8, hi_m=(o%16)/8
// idx = ((ks*16+ob)*32 + 4*g+t)*4 + (hi_m + 2*hi_k)
__global__ void fold_all_kernel(
    const float* __restrict__ wq, const float* __restrict__ bq, const float* __restrict__ gq,
    const float* __restrict__ betaq, const float* __restrict__ mq, const float* __restrict__ varq,
    const float* __restrict__ wk, const float* __restrict__ bk, const float* __restrict__ gk,
    const float* __restrict__ betak, const float* __restrict__ mk, const float* __restrict__ vark,
    const float* __restrict__ wv, const float* __restrict__ bv, const float* __restrict__ gv,
    const float* __restrict__ betav, const float* __restrict__ mv, const float* __restrict__ varv,
    const float* __restrict__ wo) {
    int o = blockIdx.x;
    int slot = blockIdx.y;
    float s = 1.f;
    if (slot < 3) {
        const float *b, *g, *beta, *mean, *var;
        if (slot == 0)      { b = bq; g = gq; beta = betaq; mean = mq; var = varq; }
        else if (slot == 1) { b = bk; g = gk; beta = betak; mean = mk; var = vark; }
        else                { b = bv; g = gv; beta = betav; mean = mv; var = varv; }
        s = g[o] * rsqrtf(var[o] + 1e-5f);
        if (threadIdx.x == 0)
            g_beff[slot * C + o] = (b[o] - mean[o]) * s + beta[o];
    }
    const float* w = (slot == 0) ? wq : (slot == 1) ? wk : (slot == 2) ? wv : wo;
    int ob = o >> 4, r = o & 15, gg = r & 7, hi_m = r >> 3;
    for (int c = threadIdx.x; c < C; c += blockDim.x) {
        int ks = c >> 3, t = c & 3, hi_k = (c >> 2) & 1;
        int idx = ((ks * 16 + ob) * 32 + 4 * gg + t) * 4 + hi_m + 2 * hi_k;
        g_wfrag[slot * C * C + idx] = f2tf32(w[o * C + c] * s);
    }
}

// ---------------- tf32 tensor-core 1x1-conv GEMM --------------------------
// OUT[b,o,l] = sum_c W[o,c]*(X[b,c,l]+PE?[c,l]) + bias[o] + RES?[b,o,l]
// Block: 128o x 32l, 4 warps (warp w -> o in [32w,32w+32)). Whole K=256 panel
// of X (tf32) staged in smem once; zero k-loop syncs.
__global__ void __launch_bounds__(128) proj_mma_kernel(
    const float* __restrict__ X, const float* __restrict__ PE,
    const uint32_t* __restrict__ Afrag, const float* __restrict__ bias,
    const float* __restrict__ RES, float* __restrict__ OUT) {
    __shared__ uint32_t Xs[C][XPAD];

    int bIdx = blockIdx.z;
    int o0 = blockIdx.y * PTO;
    int l0 = blockIdx.x * PTL;
    int tid = threadIdx.x;
    int w = tid >> 5, lane = tid & 31;
    int g = lane >> 2, t = lane & 3;

    const float* Xb = X + (size_t)bIdx * C * L;

    // ---- stage X(+PE) panel as tf32: [256c x 32l] ----
    {
        int l4 = (tid & 7) * 4;
        int cr = tid >> 3;  // 0..15
#pragma unroll
        for (int i = 0; i < 16; i++) {
            int c = cr + 16 * i;
            float4 xv = *(const float4*)&Xb[(size_t)c * L + l0 + l4];
            if (PE) {
                float4 pv = *(const float4*)&PE[(size_t)c * L + l0 + l4];
                xv.x += pv.x; xv.y += pv.y; xv.z += pv.z; xv.w += pv.w;
            }
            uint4 tv = make_uint4(f2tf32(xv.x), f2tf32(xv.y), f2tf32(xv.z), f2tf32(xv.w));
            *(uint4*)&Xs[c][l4] = tv;
        }
    }
    __syncthreads();

    // ---- mainloop: 32 k-steps of 8 ----
    float acc[2][4][4] = {};
    int ob0 = blockIdx.y * 8 + 2 * w;  // m-tile 0; m-tile 1 = ob0+1
#pragma unroll 4
    for (int ks = 0; ks < 32; ks++) {
        uint4 a0v = *(const uint4*)&Afrag[((ks * 16 + ob0) * 32 + lane) * 4];
        uint4 a1v = *(const uint4*)&Afrag[((ks * 16 + ob0 + 1) * 32 + lane) * 4];
        uint32_t a0[4] = {a0v.x, a0v.y, a0v.z, a0v.w};
        uint32_t a1[4] = {a1v.x, a1v.y, a1v.z, a1v.w};
#pragma unroll
        for (int nt = 0; nt < 4; nt++) {
            uint32_t b0 = Xs[8 * ks + t][8 * nt + g];
            uint32_t b1 = Xs[8 * ks + t + 4][8 * nt + g];
            mma_tf32(acc[0][nt], a0, b0, b1);
            mma_tf32(acc[1][nt], a1, b0, b1);
        }
    }

    // ---- epilogue: bias + optional residual, float2 stores ----
#pragma unroll
    for (int mt = 0; mt < 2; mt++) {
        int oA = o0 + 32 * w + 16 * mt + g;      // rows oA, oA+8
        float biA = bias[oA], biB = bias[oA + 8];
        size_t rowA = ((size_t)bIdx * C + oA) * L;
        size_t rowB = rowA + 8 * (size_t)L;
#pragma unroll
        for (int nt = 0; nt < 4; nt++) {
            int l = l0 + 8 * nt + 2 * t;
            float2 vA = {acc[mt][nt][0] + biA, acc[mt][nt][1] + biA};
            float2 vB = {acc[mt][nt][2] + biB, acc[mt][nt][3] + biB};
            if (RES) {
                float2 rA = *(const float2*)&RES[rowA + l];
                float2 rB = *(const float2*)&RES[rowB + l];
                vA.x += rA.x; vA.y += rA.y;
                vB.x += rB.x; vB.y += rB.y;
            }
            *(float2*)&OUT[rowA + l] = vA;
            *(float2*)&OUT[rowB + l] = vB;
        }
    }
}

// ---------------- flash attention: tf32 QK + bf16 PV via mma.sync ----------
__global__ void __launch_bounds__(128) attn_kernel(
    const float* __restrict__ qp, const float* __restrict__ kp,
    const float* __restrict__ vp, float* __restrict__ outa) {
    __shared__ uint32_t KtA[16][72];
    __shared__ uint32_t KtB[16][72];
    __shared__ uint32_t Vt[32][36];

    int b = blockIdx.z, h = blockIdx.y;
    int tid = threadIdx.x;
    int w = tid >> 5, lane = tid & 31;
    int g = lane >> 2, t = lane & 3;
    int q0 = blockIdx.x * NQT;
    int cbase = b * C + h * D;
    const float scl = 0.17677669529663687f * 1.4426950408889634f;  // (1/sqrt(D))*log2(e)

    uint32_t qa[4][4];
    {
        int qrow = q0 + 16 * w;
#pragma unroll
        for (int ks = 0; ks < 4; ks++) {
            int d0 = 8 * ks;
            qa[ks][0] = f2tf32(qp[(size_t)(cbase + d0 + t) * L + qrow + g] * scl);
            qa[ks][1] = f2tf32(qp[(size_t)(cbase + d0 + t) * L + qrow + g + 8] * scl);
            qa[ks][2] = f2tf32(qp[(size_t)(cbase + d0 + t + 4) * L + qrow + g] * scl);
            qa[ks][3] = f2tf32(qp[(size_t)(cbase + d0 + t + 4) * L + qrow + g + 8] * scl);
        }
    }

    float accPV[4][4] = {};
    float mA = -CUDART_INF_F, mB = -CUDART_INF_F, lA = 0.f, lB = 0.f;

    float kreg[16];
    float2 vreg[8];
    int kd_hi = tid >> 6, kkey = tid & 63;
    int vd_hi = tid >> 5, vkp = tid & 31;

#pragma unroll
    for (int p = 0; p < 16; p++)
        kreg[p] = kp[(size_t)(cbase + 2 * p + kd_hi) * L + kkey];
#pragma unroll
    for (int p = 0; p < 8; p++)
        vreg[p] = *(const float2*)&vp[(size_t)(cbase + 4 * p + vd_hi) * L + 2 * vkp];

    for (int kt = 0; kt < L; kt += NKT) {
        __syncthreads();
#pragma unroll
        for (int p = 0; p < 16; p++) {
            int d = 2 * p + kd_hi;
            int s = ((d >> 3) << 2) | (d & 3);
            uint32_t tv = f2tf32(kreg[p]);
            if (((d >> 2) & 1) == 0) KtA[s][kkey] = tv;
            else                     KtB[s][kkey] = tv;
        }
#pragma unroll
        for (int p = 0; p < 8; p++) {
            int d = 4 * p + vd_hi;
            Vt[d][vkp] = bfpk(vreg[p].y, vreg[p].x);
        }
        __syncthreads();

        if (kt + NKT < L) {
            int kn = kt + NKT;
#pragma unroll
            for (int p = 0; p < 16; p++)
                kreg[p] = kp[(size_t)(cbase + 2 * p + kd_hi) * L + kn + kkey];
#pragma unroll
            for (int p = 0; p < 8; p++)
                vreg[p] = *(const float2*)&vp[(size_t)(cbase + 4 * p + vd_hi) * L + kn + 2 * vkp];
        }

        float c[8][4] = {};
#pragma unroll
        for (int n = 0; n < 8; n++) {
#pragma unroll
            for (int ks = 0; ks < 4; ks++) {
                uint32_t b0 = KtA[4 * ks + t][8 * n + g];
                uint32_t b1 = KtB[4 * ks + t][8 * n + g];
                mma_tf32(c[n], qa[ks], b0, b1);
            }
        }

        float tA = -CUDART_INF_F, tB = -CUDART_INF_F;
#pragma unroll
        for (int n = 0; n < 8; n++) {
            tA = fmaxf(tA, fmaxf(c[n][0], c[n][1]));
            tB = fmaxf(tB, fmaxf(c[n][2], c[n][3]));
        }
        tA = fmaxf(tA, __shfl_xor_sync(0xffffffffu, tA, 1));
        tA = fmaxf(tA, __shfl_xor_sync(0xffffffffu, tA, 2));
        tB = fmaxf(tB, __shfl_xor_sync(0xffffffffu, tB, 1));
        tB = fmaxf(tB, __shfl_xor_sync(0xffffffffu, tB, 2));
        float mAn = fmaxf(mA, tA), mBn = fmaxf(mB, tB);
        float cA = ex2(mA - mAn), cB = ex2(mB - mBn);
        mA = mAn; mB = mBn;
        lA *= cA; lB *= cB;
#pragma unroll
        for (int nt = 0; nt < 4; nt++) {
            accPV[nt][0] *= cA; accPV[nt][1] *= cA;
            accPV[nt][2] *= cB; accPV[nt][3] *= cB;
        }
#pragma unroll
        for (int n = 0; n < 8; n++) {
            c[n][0] = ex2(c[n][0] - mA); c[n][1] = ex2(c[n][1] - mA);
            c[n][2] = ex2(c[n][2] - mB); c[n][3] = ex2(c[n][3] - mB);
            lA += c[n][0] + c[n][1];
            lB += c[n][2] + c[n][3];
        }

#pragma unroll
        for (int kk = 0; kk < 4; kk++) {
            uint32_t a0 = bfpk(c[2 * kk][1],     c[2 * kk][0]);
            uint32_t a1 = bfpk(c[2 * kk][3],     c[2 * kk][2]);
            uint32_t a2 = bfpk(c[2 * kk + 1][1], c[2 * kk + 1][0]);
            uint32_t a3 = bfpk(c[2 * kk + 1][3], c[2 * kk + 1][2]);
#pragma unroll
            for (int nt = 0; nt < 4; nt++) {
                uint32_t b0 = Vt[8 * nt + g][8 * kk + t];
                uint32_t b1 = Vt[8 * nt + g][8 * kk + t + 4];
                mma_bf16(accPV[nt], a0, a1, a2, a3, b0, b1);
            }
        }
    }

    lA += __shfl_xor_sync(0xffffffffu, lA, 1);
    lA += __shfl_xor_sync(0xffffffffu, lA, 2);
    lB += __shfl_xor_sync(0xffffffffu, lB, 1);
    lB += __shfl_xor_sync(0xffffffffu, lB, 2);
    float iA = 1.f / lA, iB = 1.f / lB;
    int q = q0 + 16 * w + g;
#pragma unroll
    for (int nt = 0; nt < 4; nt++) {
        int d = 8 * nt + 2 * t;
        outa[(size_t)(cbase + d) * L + q]         = accPV[nt][0] * iA;
        outa[(size_t)(cbase + d + 1) * L + q]     = accPV[nt][1] * iA;
        outa[(size_t)(cbase + d) * L + q + 8]     = accPV[nt][2] * iB;
        outa[(size_t)(cbase + d + 1) * L + q + 8] = accPV[nt][3] * iB;
    }
}

// ---------------- launch ----------------
extern "C" void kernel_launch(void* const* d_in, const int* in_sizes, int n_in,
                              void* d_out, int out_size) {
    const float* v     = (const float*)d_in[0];
    const float* k     = (const float*)d_in[1];
    const float* q     = (const float*)d_in[2];
    const float* pe_q  = (const float*)d_in[3];
    const float* pe_vk = (const float*)d_in[4];
    const float* wq = (const float*)d_in[5],  *bq = (const float*)d_in[6];
    const float* gq = (const float*)d_in[7],  *betaq = (const float*)d_in[8];
    const float* mq = (const float*)d_in[9],  *varq = (const float*)d_in[10];
    const float* wk = (const float*)d_in[11], *bk = (const float*)d_in[12];
    const float* gk = (const float*)d_in[13], *betak = (const float*)d_in[14];
    const float* mk = (const float*)d_in[15], *vark = (const float*)d_in[16];
    const float* wv = (const float*)d_in[17], *bv = (const float*)d_in[18];
    const float* gv = (const float*)d_in[19], *betav = (const float*)d_in[20];
    const float* mv = (const float*)d_in[21], *varv = (const float*)d_in[22];
    const float* wo = (const float*)d_in[23], *bo = (const float*)d_in[24];
    float* out = (float*)d_out;

    uint32_t* p_wfrag;
    float *p_beff, *p_qp, *p_kp, *p_vp, *p_att;
    cudaGetSymbolAddress((void**)&p_wfrag, g_wfrag);
    cudaGetSymbolAddress((void**)&p_beff, g_beff);
    cudaGetSymbolAddress((void**)&p_qp,  g_qp);
    cudaGetSymbolAddress((void**)&p_kp,  g_kp);
    cudaGetSymbolAddress((void**)&p_vp,  g_vp);
    cudaGetSymbolAddress((void**)&p_att, g_att);

    // fold BN + emit tf32 A-frag layouts (q/k/v folded, wo plain)
    fold_all_kernel<<<dim3(C, 4), 256>>>(wq, bq, gq, betaq, mq, varq,
                                         wk, bk, gk, betak, mk, vark,
                                         wv, bv, gv, betav, mv, varv, wo);

    dim3 pgrid(L / PTL, C / PTO, BB);
    proj_mma_kernel<<<pgrid, 128>>>(q, pe_q,  p_wfrag + 0 * C * C, p_beff + 0 * C, nullptr, p_qp);
    proj_mma_kernel<<<pgrid, 128>>>(k, pe_vk, p_wfrag + 1 * C * C, p_beff + 1 * C, nullptr, p_kp);
    proj_mma_kernel<<<pgrid, 128>>>(v, pe_vk, p_wfrag + 2 * C * C, p_beff + 2 * C, nullptr, p_vp);

    // tensor-core flash attention
    attn_kernel<<<dim3(L / NQT, H, BB), 128>>>(p_qp, p_kp, p_vp, p_att);

    // output projection + residual
    proj_mma_kernel<<<pgrid, 128>>>(p_att, nullptr, p_wfrag + 3 * C * C, bo, q, out);
}

// round 10
// speedup vs baseline: 3.7654x; 1.4734x over previous
#include <cuda_runtime.h>
#include <math_constants.h>
#include <cstdint>

#define BB 4
#define C 256
#define L 2048
#define H 8
#define D 32
#define NQT 64   // attn: queries per block
#define NKT 64   // attn: keys per tile
#define PTL 32   // proj: l-cols per block
#define PTO 128  // proj: o-rows per block
#define XPAD 40  // proj smem row stride (words): bank = 8t+g+8n, conflict-free

// ---------------- device scratch (no allocations allowed) ----------------
__device__ uint32_t g_wfrag[4 * C * C];  // tf32 A-fragment-layout weights (slots 0..3)
__device__ float g_beff[3 * C];
__device__ float g_qp[BB * C * L];
__device__ float g_kp[BB * C * L];
__device__ float g_vp[BB * C * L];
__device__ float g_att[BB * C * L];

// ---------------- helpers ----------------
__device__ __forceinline__ float ex2(float x) {
    float y;
    asm("ex2.approx.ftz.f32 %0, %1;" : "=f"(y) : "f"(x));
    return y;
}
__device__ __forceinline__ uint32_t f2tf32(float x) {
    uint32_t r;
    asm("cvt.rna.tf32.f32 %0, %1;" : "=r"(r) : "f"(x));
    return r;
}
// packs: hi -> upper 16 bits, lo -> lower 16 bits
__device__ __forceinline__ uint32_t bfpk(float hi, float lo) {
    uint32_t r;
    asm("cvt.rn.bf16x2.f32 %0, %1, %2;" : "=r"(r) : "f"(hi), "f"(lo));
    return r;
}
__device__ __forceinline__ void mma_tf32(float c[4], const uint32_t a[4],
                                         uint32_t b0, uint32_t b1) {
    asm volatile(
        "mma.sync.aligned.m16n8k8.row.col.f32.tf32.tf32.f32 "
        "{%0,%1,%2,%3},{%4,%5,%6,%7},{%8,%9},{%0,%1,%2,%3};"
        : "+f"(c[0]), "+f"(c[1]), "+f"(c[2]), "+f"(c[3])
        : "r"(a[0]), "r"(a[1]), "r"(a[2]), "r"(a[3]), "r"(b0), "r"(b1));
}
__device__ __forceinline__ void mma_bf16(float c[4], uint32_t a0, uint32_t a1,
                                         uint32_t a2, uint32_t a3,
                                         uint32_t b0, uint32_t b1) {
    asm volatile(
        "mma.sync.aligned.m16n8k16.row.col.f32.bf16.bf16.f32 "
        "{%0,%1,%2,%3},{%4,%5,%6,%7},{%8,%9},{%0,%1,%2,%3};"
        : "+f"(c[0]), "+f"(c[1]), "+f"(c[2]), "+f"(c[3])
        : "r"(a0), "r"(a1), "r"(a2), "r"(a3), "r"(b0), "r"(b1));
}

// ---------------- fold BN + emit tf32 A-fragment layout (q/k/v) -----------
// For (o,c): ks=c/8, t=c%4, hi_k=(c>>2)&1; ob=o/16, g=(o%16)%8, hi_m=(o%16)/8
// idx = ((ks*16+ob)*32 + 4*g+t)*4 + (hi_m + 2*hi_k)
__global__ void fold_qkv_kernel(
    const float* __restrict__ wq, const float* __restrict__ bq, const float* __restrict__ gq,
    const float* __restrict__ betaq, const float* __restrict__ mq, const float* __restrict__ varq,
    const float* __restrict__ wk, const float* __restrict__ bk, const float* __restrict__ gk,
    const float* __restrict__ betak, const float* __restrict__ mk, const float* __restrict__ vark,
    const float* __restrict__ wv, const float* __restrict__ bv, const float* __restrict__ gv,
    const float* __restrict__ betav, const float* __restrict__ mv, const float* __restrict__ varv) {
    int o = blockIdx.x;
    int slot = blockIdx.y;
    const float *w, *b, *g, *beta, *mean, *var;
    if (slot == 0)      { w = wq; b = bq; g = gq; beta = betaq; mean = mq; var = varq; }
    else if (slot == 1) { w = wk; b = bk; g = gk; beta = betak; mean = mk; var = vark; }
    else                { w = wv; b = bv; g = gv; beta = betav; mean = mv; var = varv; }
    float s = g[o] * rsqrtf(var[o] + 1e-5f);
    if (threadIdx.x == 0)
        g_beff[slot * C + o] = (b[o] - mean[o]) * s + beta[o];
    int ob = o >> 4, r = o & 15, gg = r & 7, hi_m = r >> 3;
    for (int c = threadIdx.x; c < C; c += blockDim.x) {
        int ks = c >> 3, t = c & 3, hi_k = (c >> 2) & 1;
        int idx = ((ks * 16 + ob) * 32 + 4 * gg + t) * 4 + hi_m + 2 * hi_k;
        g_wfrag[slot * C * C + idx] = f2tf32(w[o * C + c] * s);
    }
}

// wo -> A-frag slot 3 (separate launch so attn lands in ncu's -s 5 window)
__global__ void fold_wo_kernel(const float* __restrict__ wo) {
    int o = blockIdx.x;
    int ob = o >> 4, r = o & 15, gg = r & 7, hi_m = r >> 3;
    for (int c = threadIdx.x; c < C; c += blockDim.x) {
        int ks = c >> 3, t = c & 3, hi_k = (c >> 2) & 1;
        int idx = ((ks * 16 + ob) * 32 + 4 * gg + t) * 4 + hi_m + 2 * hi_k;
        g_wfrag[3 * C * C + idx] = f2tf32(wo[o * C + c]);
    }
}

// ---------------- tf32 tensor-core 1x1-conv GEMM --------------------------
// OUT[b,o,l] = sum_c W[o,c]*(X[b,c,l]+PE?[c,l]) + bias[o] + RES?[b,o,l]
// Block: 128o x 32l, 8 warps (warp w -> ONE 16-row m-tile). Whole K=256 panel
// of X (tf32) staged in smem once; zero k-loop syncs. 256 threads doubles
// warps/SM vs the 4-warp version (occupancy was the binding limit).
__global__ void __launch_bounds__(256) proj_mma_kernel(
    const float* __restrict__ X, const float* __restrict__ PE,
    const uint32_t* __restrict__ Afrag, const float* __restrict__ bias,
    const float* __restrict__ RES, float* __restrict__ OUT) {
    __shared__ uint32_t Xs[C][XPAD];

    int bIdx = blockIdx.z;
    int o0 = blockIdx.y * PTO;
    int l0 = blockIdx.x * PTL;
    int tid = threadIdx.x;
    int w = tid >> 5, lane = tid & 31;
    int g = lane >> 2, t = lane & 3;

    const float* Xb = X + (size_t)bIdx * C * L;

    // ---- stage X(+PE) panel as tf32: [256c x 32l] ----
    {
        int l4 = (tid & 7) * 4;
        int cr = tid >> 3;  // 0..31
#pragma unroll
        for (int i = 0; i < 8; i++) {
            int c = cr + 32 * i;
            float4 xv = *(const float4*)&Xb[(size_t)c * L + l0 + l4];
            if (PE) {
                float4 pv = *(const float4*)&PE[(size_t)c * L + l0 + l4];
                xv.x += pv.x; xv.y += pv.y; xv.z += pv.z; xv.w += pv.w;
            }
            uint4 tv = make_uint4(f2tf32(xv.x), f2tf32(xv.y), f2tf32(xv.z), f2tf32(xv.w));
            *(uint4*)&Xs[c][l4] = tv;
        }
    }
    __syncthreads();

    // ---- mainloop: 32 k-steps of 8; one m-tile per warp ----
    float acc[4][4] = {};
    int ob = blockIdx.y * 8 + w;
#pragma unroll 4
    for (int ks = 0; ks < 32; ks++) {
        uint4 av = *(const uint4*)&Afrag[((ks * 16 + ob) * 32 + lane) * 4];
        uint32_t a[4] = {av.x, av.y, av.z, av.w};
#pragma unroll
        for (int nt = 0; nt < 4; nt++) {
            uint32_t b0 = Xs[8 * ks + t][8 * nt + g];
            uint32_t b1 = Xs[8 * ks + t + 4][8 * nt + g];
            mma_tf32(acc[nt], a, b0, b1);
        }
    }

    // ---- epilogue: bias + optional residual, float2 stores ----
    {
        int oA = o0 + 16 * w + g;                // rows oA, oA+8
        float biA = bias[oA], biB = bias[oA + 8];
        size_t rowA = ((size_t)bIdx * C + oA) * L;
        size_t rowB = rowA + 8 * (size_t)L;
#pragma unroll
        for (int nt = 0; nt < 4; nt++) {
            int l = l0 + 8 * nt + 2 * t;
            float2 vA = {acc[nt][0] + biA, acc[nt][1] + biA};
            float2 vB = {acc[nt][2] + biB, acc[nt][3] + biB};
            if (RES) {
                float2 rA = *(const float2*)&RES[rowA + l];
                float2 rB = *(const float2*)&RES[rowB + l];
                vA.x += rA.x; vA.y += rA.y;
                vB.x += rB.x; vB.y += rB.y;
            }
            *(float2*)&OUT[rowA + l] = vA;
            *(float2*)&OUT[rowB + l] = vB;
        }
    }
}

// ---------------- flash attention: tf32 QK + bf16 PV via mma.sync ----------
__global__ void __launch_bounds__(128) attn_kernel(
    const float* __restrict__ qp, const float* __restrict__ kp,
    const float* __restrict__ vp, float* __restrict__ outa) {
    __shared__ uint32_t KtA[16][72];
    __shared__ uint32_t KtB[16][72];
    __shared__ uint32_t Vt[32][36];

    int b = blockIdx.z, h = blockIdx.y;
    int tid = threadIdx.x;
    int w = tid >> 5, lane = tid & 31;
    int g = lane >> 2, t = lane & 3;
    int q0 = blockIdx.x * NQT;
    int cbase = b * C + h * D;
    const float scl = 0.17677669529663687f * 1.4426950408889634f;  // (1/sqrt(D))*log2(e)

    uint32_t qa[4][4];
    {
        int qrow = q0 + 16 * w;
#pragma unroll
        for (int ks = 0; ks < 4; ks++) {
            int d0 = 8 * ks;
            qa[ks][0] = f2tf32(qp[(size_t)(cbase + d0 + t) * L + qrow + g] * scl);
            qa[ks][1] = f2tf32(qp[(size_t)(cbase + d0 + t) * L + qrow + g + 8] * scl);
            qa[ks][2] = f2tf32(qp[(size_t)(cbase + d0 + t + 4) * L + qrow + g] * scl);
            qa[ks][3] = f2tf32(qp[(size_t)(cbase + d0 + t + 4) * L + qrow + g + 8] * scl);
        }
    }

    float accPV[4][4] = {};
    float mA = -CUDART_INF_F, mB = -CUDART_INF_F, lA = 0.f, lB = 0.f;

    float kreg[16];
    float2 vreg[8];
    int kd_hi = tid >> 6, kkey = tid & 63;
    int vd_hi = tid >> 5, vkp = tid & 31;

#pragma unroll
    for (int p = 0; p < 16; p++)
        kreg[p] = kp[(size_t)(cbase + 2 * p + kd_hi) * L + kkey];
#pragma unroll
    for (int p = 0; p < 8; p++)
        vreg[p] = *(const float2*)&vp[(size_t)(cbase + 4 * p + vd_hi) * L + 2 * vkp];

    for (int kt = 0; kt < L; kt += NKT) {
        __syncthreads();
#pragma unroll
        for (int p = 0; p < 16; p++) {
            int d = 2 * p + kd_hi;
            int s = ((d >> 3) << 2) | (d & 3);
            uint32_t tv = f2tf32(kreg[p]);
            if (((d >> 2) & 1) == 0) KtA[s][kkey] = tv;
            else                     KtB[s][kkey] = tv;
        }
#pragma unroll
        for (int p = 0; p < 8; p++) {
            int d = 4 * p + vd_hi;
            Vt[d][vkp] = bfpk(vreg[p].y, vreg[p].x);
        }
        __syncthreads();

        if (kt + NKT < L) {
            int kn = kt + NKT;
#pragma unroll
            for (int p = 0; p < 16; p++)
                kreg[p] = kp[(size_t)(cbase + 2 * p + kd_hi) * L + kn + kkey];
#pragma unroll
            for (int p = 0; p < 8; p++)
                vreg[p] = *(const float2*)&vp[(size_t)(cbase + 4 * p + vd_hi) * L + kn + 2 * vkp];
        }

        float c[8][4] = {};
#pragma unroll
        for (int n = 0; n < 8; n++) {
#pragma unroll
            for (int ks = 0; ks < 4; ks++) {
                uint32_t b0 = KtA[4 * ks + t][8 * n + g];
                uint32_t b1 = KtB[4 * ks + t][8 * n + g];
                mma_tf32(c[n], qa[ks], b0, b1);
            }
        }

        float tA = -CUDART_INF_F, tB = -CUDART_INF_F;
#pragma unroll
        for (int n = 0; n < 8; n++) {
            tA = fmaxf(tA, fmaxf(c[n][0], c[n][1]));
            tB = fmaxf(tB, fmaxf(c[n][2], c[n][3]));
        }
        tA = fmaxf(tA, __shfl_xor_sync(0xffffffffu, tA, 1));
        tA = fmaxf(tA, __shfl_xor_sync(0xffffffffu, tA, 2));
        tB = fmaxf(tB, __shfl_xor_sync(0xffffffffu, tB, 1));
        tB = fmaxf(tB, __shfl_xor_sync(0xffffffffu, tB, 2));
        float mAn = fmaxf(mA, tA), mBn = fmaxf(mB, tB);
        float cA = ex2(mA - mAn), cB = ex2(mB - mBn);
        mA = mAn; mB = mBn;
        lA *= cA; lB *= cB;
#pragma unroll
        for (int nt = 0; nt < 4; nt++) {
            accPV[nt][0] *= cA; accPV[nt][1] *= cA;
            accPV[nt][2] *= cB; accPV[nt][3] *= cB;
        }
#pragma unroll
        for (int n = 0; n < 8; n++) {
            c[n][0] = ex2(c[n][0] - mA); c[n][1] = ex2(c[n][1] - mA);
            c[n][2] = ex2(c[n][2] - mB); c[n][3] = ex2(c[n][3] - mB);
            lA += c[n][0] + c[n][1];
            lB += c[n][2] + c[n][3];
        }

#pragma unroll
        for (int kk = 0; kk < 4; kk++) {
            uint32_t a0 = bfpk(c[2 * kk][1],     c[2 * kk][0]);
            uint32_t a1 = bfpk(c[2 * kk][3],     c[2 * kk][2]);
            uint32_t a2 = bfpk(c[2 * kk + 1][1], c[2 * kk + 1][0]);
            uint32_t a3 = bfpk(c[2 * kk + 1][3], c[2 * kk + 1][2]);
#pragma unroll
            for (int nt = 0; nt < 4; nt++) {
                uint32_t b0 = Vt[8 * nt + g][8 * kk + t];
                uint32_t b1 = Vt[8 * nt + g][8 * kk + t + 4];
                mma_bf16(accPV[nt], a0, a1, a2, a3, b0, b1);
            }
        }
    }

    lA += __shfl_xor_sync(0xffffffffu, lA, 1);
    lA += __shfl_xor_sync(0xffffffffu, lA, 2);
    lB += __shfl_xor_sync(0xffffffffu, lB, 1);
    lB += __shfl_xor_sync(0xffffffffu, lB, 2);
    float iA = 1.f / lA, iB = 1.f / lB;
    int q = q0 + 16 * w + g;
#pragma unroll
    for (int nt = 0; nt < 4; nt++) {
        int d = 8 * nt + 2 * t;
        outa[(size_t)(cbase + d) * L + q]         = accPV[nt][0] * iA;
        outa[(size_t)(cbase + d + 1) * L + q]     = accPV[nt][1] * iA;
        outa[(size_t)(cbase + d) * L + q + 8]     = accPV[nt][2] * iB;
        outa[(size_t)(cbase + d + 1) * L + q + 8] = accPV[nt][3] * iB;
    }
}

// ---------------- launch ----------------
extern "C" void kernel_launch(void* const* d_in, const int* in_sizes, int n_in,
                              void* d_out, int out_size) {
    const float* v     = (const float*)d_in[0];
    const float* k     = (const float*)d_in[1];
    const float* q     = (const float*)d_in[2];
    const float* pe_q  = (const float*)d_in[3];
    const float* pe_vk = (const float*)d_in[4];
    const float* wq = (const float*)d_in[5],  *bq = (const float*)d_in[6];
    const float* gq = (const float*)d_in[7],  *betaq = (const float*)d_in[8];
    const float* mq = (const float*)d_in[9],  *varq = (const float*)d_in[10];
    const float* wk = (const float*)d_in[11], *bk = (const float*)d_in[12];
    const float* gk = (const float*)d_in[13], *betak = (const float*)d_in[14];
    const float* mk = (const float*)d_in[15], *vark = (const float*)d_in[16];
    const float* wv = (const float*)d_in[17], *bv = (const float*)d_in[18];
    const float* gv = (const float*)d_in[19], *betav = (const float*)d_in[20];
    const float* mv = (const float*)d_in[21], *varv = (const float*)d_in[22];
    const float* wo = (const float*)d_in[23], *bo = (const float*)d_in[24];
    float* out = (float*)d_out;

    uint32_t* p_wfrag;
    float *p_beff, *p_qp, *p_kp, *p_vp, *p_att;
    cudaGetSymbolAddress((void**)&p_wfrag, g_wfrag);
    cudaGetSymbolAddress((void**)&p_beff, g_beff);
    cudaGetSymbolAddress((void**)&p_qp,  g_qp);
    cudaGetSymbolAddress((void**)&p_kp,  g_kp);
    cudaGetSymbolAddress((void**)&p_vp,  g_vp);
    cudaGetSymbolAddress((void**)&p_att, g_att);

    // launches 1-2: weight prep (split so attn is launch #6 = ncu -s 5 target)
    fold_qkv_kernel<<<dim3(C, 3), 256>>>(wq, bq, gq, betaq, mq, varq,
                                         wk, bk, gk, betak, mk, vark,
                                         wv, bv, gv, betav, mv, varv);
    fold_wo_kernel<<<C, 256>>>(wo);

    dim3 pgrid(L / PTL, C / PTO, BB);
    // launches 3-5
    proj_mma_kernel<<<pgrid, 256>>>(q, pe_q,  p_wfrag + 0 * C * C, p_beff + 0 * C, nullptr, p_qp);
    proj_mma_kernel<<<pgrid, 256>>>(k, pe_vk, p_wfrag + 1 * C * C, p_beff + 1 * C, nullptr, p_kp);
    proj_mma_kernel<<<pgrid, 256>>>(v, pe_vk, p_wfrag + 2 * C * C, p_beff + 2 * C, nullptr, p_vp);

    // launch 6: tensor-core flash attention (ncu target)
    attn_kernel<<<dim3(L / NQT, H, BB), 128>>>(p_qp, p_kp, p_vp, p_att);

    // launch 7: output projection + residual
    proj_mma_kernel<<<pgrid, 256>>>(p_att, nullptr, p_wfrag + 3 * C * C, bo, q, out);
}

// round 15
// speedup vs baseline: 4.1279x; 1.0963x over previous
#include <cuda_runtime.h>
#include <math_constants.h>
#include <cstdint>

#define BB 4
#define C 256
#define L 2048
#define H 8
#define D 32
#define NQT 128  // attn: queries per block (8 warps x 16 rows)
#define NKT 64   // attn: keys per tile
#define PTL 32   // proj: l-cols per block
#define PTO 128  // proj: o-rows per block
#define XPAD 40  // proj smem row stride (words)

// ---------------- device scratch (no allocations allowed) ----------------
__device__ uint32_t g_wfrag[4 * C * C];  // tf32 A-fragment-layout weights (slots 0..3)
__device__ float g_beff[3 * C];
__device__ float g_qp[BB * C * L];
__device__ float g_kp[BB * C * L];
__device__ float g_vp[BB * C * L];
__device__ float g_att[BB * C * L];

// ---------------- helpers ----------------
__device__ __forceinline__ float ex2(float x) {
    float y;
    asm("ex2.approx.ftz.f32 %0, %1;" : "=f"(y) : "f"(x));
    return y;
}
__device__ __forceinline__ uint32_t f2tf32(float x) {
    uint32_t r;
    asm("cvt.rna.tf32.f32 %0, %1;" : "=r"(r) : "f"(x));
    return r;
}
// packs: hi -> upper 16 bits, lo -> lower 16 bits
__device__ __forceinline__ uint32_t bfpk(float hi, float lo) {
    uint32_t r;
    asm("cvt.rn.bf16x2.f32 %0, %1, %2;" : "=r"(r) : "f"(hi), "f"(lo));
    return r;
}
__device__ __forceinline__ void mma_tf32(float c[4], const uint32_t a[4],
                                         uint32_t b0, uint32_t b1) {
    asm volatile(
        "mma.sync.aligned.m16n8k8.row.col.f32.tf32.tf32.f32 "
        "{%0,%1,%2,%3},{%4,%5,%6,%7},{%8,%9},{%0,%1,%2,%3};"
        : "+f"(c[0]), "+f"(c[1]), "+f"(c[2]), "+f"(c[3])
        : "r"(a[0]), "r"(a[1]), "r"(a[2]), "r"(a[3]), "r"(b0), "r"(b1));
}
__device__ __forceinline__ void mma_bf16(float c[4], uint32_t a0, uint32_t a1,
                                         uint32_t a2, uint32_t a3,
                                         uint32_t b0, uint32_t b1) {
    asm volatile(
        "mma.sync.aligned.m16n8k16.row.col.f32.bf16.bf16.f32 "
        "{%0,%1,%2,%3},{%4,%5,%6,%7},{%8,%9},{%0,%1,%2,%3};"
        : "+f"(c[0]), "+f"(c[1]), "+f"(c[2]), "+f"(c[3])
        : "r"(a0), "r"(a1), "r"(a2), "r"(a3), "r"(b0), "r"(b1));
}

// ---------------- fold BN + emit tf32 A-fragment layout (q/k/v) -----------
// For (o,c): ks=c/8, t=c%4, hi_k=(c>>2)&1; ob=o/16, g=(o%16)%8, hi_m=(o%16)/8
// idx = ((ks*16+ob)*32 + 4*g+t)*4 + (hi_m + 2*hi_k)
__global__ void fold_qkv_kernel(
    const float* __restrict__ wq, const float* __restrict__ bq, const float* __restrict__ gq,
    const float* __restrict__ betaq, const float* __restrict__ mq, const float* __restrict__ varq,
    const float* __restrict__ wk, const float* __restrict__ bk, const float* __restrict__ gk,
    const float* __restrict__ betak, const float* __restrict__ mk, const float* __restrict__ vark,
    const float* __restrict__ wv, const float* __restrict__ bv, const float* __restrict__ gv,
    const float* __restrict__ betav, const float* __restrict__ mv, const float* __restrict__ varv) {
    int o = blockIdx.x;
    int slot = blockIdx.y;
    const float *w, *b, *g, *beta, *mean, *var;
    if (slot == 0)      { w = wq; b = bq; g = gq; beta = betaq; mean = mq; var = varq; }
    else if (slot == 1) { w = wk; b = bk; g = gk; beta = betak; mean = mk; var = vark; }
    else                { w = wv; b = bv; g = gv; beta = betav; mean = mv; var = varv; }
    float s = g[o] * rsqrtf(var[o] + 1e-5f);
    if (threadIdx.x == 0)
        g_beff[slot * C + o] = (b[o] - mean[o]) * s + beta[o];
    int ob = o >> 4, r = o & 15, gg = r & 7, hi_m = r >> 3;
    for (int c = threadIdx.x; c < C; c += blockDim.x) {
        int ks = c >> 3, t = c & 3, hi_k = (c >> 2) & 1;
        int idx = ((ks * 16 + ob) * 32 + 4 * gg + t) * 4 + hi_m + 2 * hi_k;
        g_wfrag[slot * C * C + idx] = f2tf32(w[o * C + c] * s);
    }
}

// wo -> A-frag slot 3
__global__ void fold_wo_kernel(const float* __restrict__ wo) {
    int o = blockIdx.x;
    int ob = o >> 4, r = o & 15, gg = r & 7, hi_m = r >> 3;
    for (int c = threadIdx.x; c < C; c += blockDim.x) {
        int ks = c >> 3, t = c & 3, hi_k = (c >> 2) & 1;
        int idx = ((ks * 16 + ob) * 32 + 4 * gg + t) * 4 + hi_m + 2 * hi_k;
        g_wfrag[3 * C * C + idx] = f2tf32(wo[o * C + c]);
    }
}

// ---------------- tf32 tensor-core 1x1-conv GEMM --------------------------
// OUT[b,o,l] = sum_c W[o,c]*(X[b,c,l]+PE?[c,l]) + bias[o] + RES?[b,o,l]
// Block: 128o x 32l, 8 warps (one 16-row m-tile per warp). X panel staged in
// smem with PERMUTED columns: Xs[c][(l&7)*4 + (l>>3)], so the 4 n-tile B-frag
// words are one LDS.128 (conflict-free at XPAD=40). Afrag software-prefetched.
__global__ void __launch_bounds__(256) proj_mma_kernel(
    const float* __restrict__ X, const float* __restrict__ PE,
    const uint32_t* __restrict__ Afrag, const float* __restrict__ bias,
    const float* __restrict__ RES, float* __restrict__ OUT) {
    __shared__ uint32_t Xs[C][XPAD];

    int bIdx = blockIdx.z;
    int o0 = blockIdx.y * PTO;
    int l0 = blockIdx.x * PTL;
    int tid = threadIdx.x;
    int w = tid >> 5, lane = tid & 31;
    int g = lane >> 2, t = lane & 3;

    const float* Xb = X + (size_t)bIdx * C * L;

    // ---- stage X(+PE) panel as tf32, permuted columns ----
    {
        int l4 = (tid & 7) * 4;
        int cr = tid >> 3;  // 0..31
#pragma unroll
        for (int i = 0; i < 8; i++) {
            int c = cr + 32 * i;
            float4 xv = *(const float4*)&Xb[(size_t)c * L + l0 + l4];
            if (PE) {
                float4 pv = *(const float4*)&PE[(size_t)c * L + l0 + l4];
                xv.x += pv.x; xv.y += pv.y; xv.z += pv.z; xv.w += pv.w;
            }
            uint32_t e[4] = {f2tf32(xv.x), f2tf32(xv.y), f2tf32(xv.z), f2tf32(xv.w)};
#pragma unroll
            for (int ii = 0; ii < 4; ii++) {
                int l = l4 + ii;
                Xs[c][((l & 7) << 2) | (l >> 3)] = e[ii];
            }
        }
    }
    __syncthreads();

    // ---- mainloop: 32 k-steps of 8; Afrag prefetched one step ahead ----
    float acc[4][4] = {};
    int ob = blockIdx.y * 8 + w;
    const uint32_t* Ab = Afrag + ((size_t)ob * 32 + lane) * 4;
    uint4 av = *(const uint4*)Ab;
#pragma unroll 4
    for (int ks = 0; ks < 32; ks++) {
        uint4 avn = av;
        if (ks + 1 < 32) avn = *(const uint4*)(Ab + (size_t)(ks + 1) * 2048);
        uint4 b0v = *(const uint4*)&Xs[8 * ks + t][g * 4];
        uint4 b1v = *(const uint4*)&Xs[8 * ks + t + 4][g * 4];
        uint32_t a[4] = {av.x, av.y, av.z, av.w};
        mma_tf32(acc[0], a, b0v.x, b1v.x);
        mma_tf32(acc[1], a, b0v.y, b1v.y);
        mma_tf32(acc[2], a, b0v.z, b1v.z);
        mma_tf32(acc[3], a, b0v.w, b1v.w);
        av = avn;
    }

    // ---- epilogue: bias + optional residual, float2 stores ----
    {
        int oA = o0 + 16 * w + g;                // rows oA, oA+8
        float biA = bias[oA], biB = bias[oA + 8];
        size_t rowA = ((size_t)bIdx * C + oA) * L;
        size_t rowB = rowA + 8 * (size_t)L;
#pragma unroll
        for (int nt = 0; nt < 4; nt++) {
            int l = l0 + 8 * nt + 2 * t;
            float2 vA = {acc[nt][0] + biA, acc[nt][1] + biA};
            float2 vB = {acc[nt][2] + biB, acc[nt][3] + biB};
            if (RES) {
                float2 rA = *(const float2*)&RES[rowA + l];
                float2 rB = *(const float2*)&RES[rowB + l];
                vA.x += rA.x; vA.y += rA.y;
                vB.x += rB.x; vB.y += rB.y;
            }
            *(float2*)&OUT[rowA + l] = vA;
            *(float2*)&OUT[rowB + l] = vB;
        }
    }
}

// ---------------- flash attention: tf32 QK + bf16 PV via mma.sync ----------
// Block = (b, h, 128-query tile), 8 warps x 16 query rows; 64-key tiles are
// shared by all 8 warps (2x the q-reuse of the 4-warp version: half the
// gmem traffic, fill work, and syncs per query). Per-warp math unchanged.
__global__ void __launch_bounds__(256) attn_kernel(
    const float* __restrict__ qp, const float* __restrict__ kp,
    const float* __restrict__ vp, float* __restrict__ outa) {
    __shared__ uint32_t KtA[16][72];
    __shared__ uint32_t KtB[16][72];
    __shared__ uint32_t Vt[32][36];

    int b = blockIdx.z, h = blockIdx.y;
    int tid = threadIdx.x;
    int w = tid >> 5, lane = tid & 31;
    int g = lane >> 2, t = lane & 3;
    int q0 = blockIdx.x * NQT;
    int cbase = b * C + h * D;
    const float scl = 0.17677669529663687f * 1.4426950408889634f;  // (1/sqrt(D))*log2(e)

    uint32_t qa[4][4];
    {
        int qrow = q0 + 16 * w;
#pragma unroll
        for (int ks = 0; ks < 4; ks++) {
            int d0 = 8 * ks;
            qa[ks][0] = f2tf32(qp[(size_t)(cbase + d0 + t) * L + qrow + g] * scl);
            qa[ks][1] = f2tf32(qp[(size_t)(cbase + d0 + t) * L + qrow + g + 8] * scl);
            qa[ks][2] = f2tf32(qp[(size_t)(cbase + d0 + t + 4) * L + qrow + g] * scl);
            qa[ks][3] = f2tf32(qp[(size_t)(cbase + d0 + t + 4) * L + qrow + g + 8] * scl);
        }
    }

    float accPV[4][4] = {};
    float mA = -CUDART_INF_F, mB = -CUDART_INF_F, lA = 0.f, lB = 0.f;

    // register-staged prefetch (256 threads: 8 K elems + 4 V pairs each)
    float kreg[8];
    float2 vreg[4];
    int kdg = tid >> 6, kkey = tid & 63;   // K elem: d = kdg + 4p, key = kkey
    int vdg = tid >> 5, vkp = tid & 31;    // V pair: d = vdg + 8p, keys 2vkp..+1

#pragma unroll
    for (int p = 0; p < 8; p++)
        kreg[p] = kp[(size_t)(cbase + kdg + 4 * p) * L + kkey];
#pragma unroll
    for (int p = 0; p < 4; p++)
        vreg[p] = *(const float2*)&vp[(size_t)(cbase + vdg + 8 * p) * L + 2 * vkp];

    for (int kt = 0; kt < L; kt += NKT) {
        __syncthreads();
#pragma unroll
        for (int p = 0; p < 8; p++) {
            int d = kdg + 4 * p;
            int s = ((d >> 3) << 2) | (d & 3);
            uint32_t tv = f2tf32(kreg[p]);
            if (((d >> 2) & 1) == 0) KtA[s][kkey] = tv;
            else                     KtB[s][kkey] = tv;
        }
#pragma unroll
        for (int p = 0; p < 4; p++) {
            int d = vdg + 8 * p;
            Vt[d][vkp] = bfpk(vreg[p].y, vreg[p].x);  // lo = even key
        }
        __syncthreads();

        if (kt + NKT < L) {  // prefetch next tile (overlaps compute)
            int kn = kt + NKT;
#pragma unroll
            for (int p = 0; p < 8; p++)
                kreg[p] = kp[(size_t)(cbase + kdg + 4 * p) * L + kn + kkey];
#pragma unroll
            for (int p = 0; p < 4; p++)
                vreg[p] = *(const float2*)&vp[(size_t)(cbase + vdg + 8 * p) * L + kn + 2 * vkp];
        }

        // ---- QK: S[16 x 64] in 8 n-tiles of C-frags ----
        float c[8][4] = {};
#pragma unroll
        for (int n = 0; n < 8; n++) {
#pragma unroll
            for (int ks = 0; ks < 4; ks++) {
                uint32_t b0 = KtA[4 * ks + t][8 * n + g];
                uint32_t b1 = KtB[4 * ks + t][8 * n + g];
                mma_tf32(c[n], qa[ks], b0, b1);
            }
        }

        // ---- online softmax (log2 domain) ----
        float tA = -CUDART_INF_F, tB = -CUDART_INF_F;
#pragma unroll
        for (int n = 0; n < 8; n++) {
            tA = fmaxf(tA, fmaxf(c[n][0], c[n][1]));
            tB = fmaxf(tB, fmaxf(c[n][2], c[n][3]));
        }
        tA = fmaxf(tA, __shfl_xor_sync(0xffffffffu, tA, 1));
        tA = fmaxf(tA, __shfl_xor_sync(0xffffffffu, tA, 2));
        tB = fmaxf(tB, __shfl_xor_sync(0xffffffffu, tB, 1));
        tB = fmaxf(tB, __shfl_xor_sync(0xffffffffu, tB, 2));
        float mAn = fmaxf(mA, tA), mBn = fmaxf(mB, tB);
        float cA = ex2(mA - mAn), cB = ex2(mB - mBn);
        mA = mAn; mB = mBn;
        lA *= cA; lB *= cB;
#pragma unroll
        for (int nt = 0; nt < 4; nt++) {
            accPV[nt][0] *= cA; accPV[nt][1] *= cA;
            accPV[nt][2] *= cB; accPV[nt][3] *= cB;
        }
#pragma unroll
        for (int n = 0; n < 8; n++) {
            c[n][0] = ex2(c[n][0] - mA); c[n][1] = ex2(c[n][1] - mA);
            c[n][2] = ex2(c[n][2] - mB); c[n][3] = ex2(c[n][3] - mB);
            lA += c[n][0] + c[n][1];
            lB += c[n][2] + c[n][3];
        }

        // ---- PV: P[16 x 64] (bf16, from C-frags) x V[64 x 32] ----
#pragma unroll
        for (int kk = 0; kk < 4; kk++) {
            uint32_t a0 = bfpk(c[2 * kk][1],     c[2 * kk][0]);
            uint32_t a1 = bfpk(c[2 * kk][3],     c[2 * kk][2]);
            uint32_t a2 = bfpk(c[2 * kk + 1][1], c[2 * kk + 1][0]);
            uint32_t a3 = bfpk(c[2 * kk + 1][3], c[2 * kk + 1][2]);
#pragma unroll
            for (int nt = 0; nt < 4; nt++) {
                uint32_t b0 = Vt[8 * nt + g][8 * kk + t];
                uint32_t b1 = Vt[8 * nt + g][8 * kk + t + 4];
                mma_bf16(accPV[nt], a0, a1, a2, a3, b0, b1);
            }
        }
    }

    lA += __shfl_xor_sync(0xffffffffu, lA, 1);
    lA += __shfl_xor_sync(0xffffffffu, lA, 2);
    lB += __shfl_xor_sync(0xffffffffu, lB, 1);
    lB += __shfl_xor_sync(0xffffffffu, lB, 2);
    float iA = 1.f / lA, iB = 1.f / lB;
    int q = q0 + 16 * w + g;
#pragma unroll
    for (int nt = 0; nt < 4; nt++) {
        int d = 8 * nt + 2 * t;
        outa[(size_t)(cbase + d) * L + q]         = accPV[nt][0] * iA;
        outa[(size_t)(cbase + d + 1) * L + q]     = accPV[nt][1] * iA;
        outa[(size_t)(cbase + d) * L + q + 8]     = accPV[nt][2] * iB;
        outa[(size_t)(cbase + d + 1) * L + q + 8] = accPV[nt][3] * iB;
    }
}

// ---------------- launch ----------------
extern "C" void kernel_launch(void* const* d_in, const int* in_sizes, int n_in,
                              void* d_out, int out_size) {
    const float* v     = (const float*)d_in[0];
    const float* k     = (const float*)d_in[1];
    const float* q     = (const float*)d_in[2];
    const float* pe_q  = (const float*)d_in[3];
    const float* pe_vk = (const float*)d_in[4];
    const float* wq = (const float*)d_in[5],  *bq = (const float*)d_in[6];
    const float* gq = (const float*)d_in[7],  *betaq = (const float*)d_in[8];
    const float* mq = (const float*)d_in[9],  *varq = (const float*)d_in[10];
    const float* wk = (const float*)d_in[11], *bk = (const float*)d_in[12];
    const float* gk = (const float*)d_in[13], *betak = (const float*)d_in[14];
    const float* mk = (const float*)d_in[15], *vark = (const float*)d_in[16];
    const float* wv = (const float*)d_in[17], *bv = (const float*)d_in[18];
    const float* gv = (const float*)d_in[19], *betav = (const float*)d_in[20];
    const float* mv = (const float*)d_in[21], *varv = (const float*)d_in[22];
    const float* wo = (const float*)d_in[23], *bo = (const float*)d_in[24];
    float* out = (float*)d_out;

    uint32_t* p_wfrag;
    float *p_beff, *p_qp, *p_kp, *p_vp, *p_att;
    cudaGetSymbolAddress((void**)&p_wfrag, g_wfrag);
    cudaGetSymbolAddress((void**)&p_beff, g_beff);
    cudaGetSymbolAddress((void**)&p_qp,  g_qp);
    cudaGetSymbolAddress((void**)&p_kp,  g_kp);
    cudaGetSymbolAddress((void**)&p_vp,  g_vp);
    cudaGetSymbolAddress((void**)&p_att, g_att);

    fold_qkv_kernel<<<dim3(C, 3), 256>>>(wq, bq, gq, betaq, mq, varq,
                                         wk, bk, gk, betak, mk, vark,
                                         wv, bv, gv, betav, mv, varv);
    fold_wo_kernel<<<C, 256>>>(wo);

    dim3 pgrid(L / PTL, C / PTO, BB);
    proj_mma_kernel<<<pgrid, 256>>>(q, pe_q,  p_wfrag + 0 * C * C, p_beff + 0 * C, nullptr, p_qp);
    proj_mma_kernel<<<pgrid, 256>>>(k, pe_vk, p_wfrag + 1 * C * C, p_beff + 1 * C, nullptr, p_kp);
    proj_mma_kernel<<<pgrid, 256>>>(v, pe_vk, p_wfrag + 2 * C * C, p_beff + 2 * C, nullptr, p_vp);

    // tensor-core flash attention (128 queries per block)
    attn_kernel<<<dim3(L / NQT, H, BB), 256>>>(p_qp, p_kp, p_vp, p_att);

    // output projection + residual
    proj_mma_kernel<<<pgrid, 256>>>(p_att, nullptr, p_wfrag + 3 * C * C, bo, q, out);
}